// round 10
// baseline (speedup 1.0000x reference)
#include <cuda_runtime.h>
#include <math.h>

#define BB 32
#define TT 200
#define TM 199
#define NN (BB*TM)        // 6368
#define DD 100
#define KK 10
#define R2 (NN*16)        // 101888
#define R1 (NN*4)         // 25472

#define NB1 531           // ceil(R1/48)  (stageC)
#define NB2 133           // ceil(NN/48)  (stageC seg2)
#define NBD 266           // ceil(NN/24)  (stageD)

// stageB mma tiling: 128 rows/block
#define MB0 796           // R2/128
#define MB1 199           // R1/128
#define MB2 50            // ceil(NN/128)

typedef unsigned long long ull;

// ---------------- scratch ----------------
__device__ float g_buf[20377600];
__device__ int   g_topk[NN*KK];

static constexpr size_t OFF_E2  = 0;          // R2*100
static constexpr size_t OFF_E1  = 10188800;   // R1*100
static constexpr size_t OFF_E0A = 12736000;   // NN*100
static constexpr size_t OFF_E1B = 13372800;   // R1*100
static constexpr size_t OFF_E0B = 15920000;   // NN*100
static constexpr size_t OFF_AGG = 16556800;   // NN*100
static constexpr size_t OFF_L   = 17193600;   // NN*100
static constexpr size_t OFF_G   = 17830400;   // NN*400

// ---------------- helpers ----------------
__device__ __forceinline__ void fma2(ull& a, ull x, ull w){
    asm("fma.rn.f32x2 %0, %1, %2, %0;" : "+l"(a) : "l"(x), "l"(w));
}
__device__ __forceinline__ float unpack_sum(ull a){
    float lo = __int_as_float((int)(unsigned int)a);
    float hi = __int_as_float((int)(unsigned int)(a >> 32));
    return lo + hi;
}
__device__ __forceinline__ float ftanh(float x){
    float e = __expf(2.f*x);
    return 1.f - __fdividef(2.f, e + 1.f);
}
__device__ __forceinline__ float fsig(float x){
    return __fdividef(1.f, 1.f + __expf(-x));
}
__device__ __forceinline__ unsigned tf32cvt(float f){
    unsigned u; asm("cvt.rna.tf32.f32 %0, %1;" : "=r"(u) : "f"(f)); return u;
}
__device__ __forceinline__ void mma_tf32(float* c, const unsigned* a, const unsigned* b){
    asm volatile("mma.sync.aligned.m16n8k8.row.col.f32.tf32.tf32.f32 "
        "{%0,%1,%2,%3}, {%4,%5,%6,%7}, {%8,%9}, {%0,%1,%2,%3};"
        : "+f"(c[0]), "+f"(c[1]), "+f"(c[2]), "+f"(c[3])
        : "r"(a[0]), "r"(a[1]), "r"(a[2]), "r"(a[3]), "r"(b[0]), "r"(b[1]));
}

// load 100x100 W into smem pitch 102 (51 ull words; conflict-free LDS.64)
__device__ __forceinline__ void loadW100(const float* __restrict__ W, float* Ws, int tid){
    for (int j = tid; j < 2500; j += 256){
        float4 v = ((const float4*)W)[j];
        int b4 = 4*j; int o = b4/100; int d = b4 - o*100;
        float2* ws = (float2*)&Ws[o*102 + d];
        ws[0] = make_float2(v.x, v.y);
        ws[1] = make_float2(v.z, v.w);
    }
}

// Software-pipelined KR-rows-per-thread 100-d FFMA core.
template<int KR>
__device__ __forceinline__ void core100p(const float* Ws, const float* Xs, int wy,
                                         const int* col, ull (*acc)[4]){
    const ull* WsU = (const ull*)Ws;
    const ull* XsU = (const ull*)Xs;
    const int xbase = wy*KR*52;
    ull w[4], x[KR], nw[4], nx[KR];
    #pragma unroll
    for (int c = 0; c < 4; c++) w[c] = WsU[col[c]*51];
    #pragma unroll
    for (int k = 0; k < KR; k++) x[k] = XsU[xbase + k*52];
    #pragma unroll 1
    for (int dw = 0; dw < 50; dw++){
        int dn = dw + 1;
        #pragma unroll
        for (int c = 0; c < 4; c++) nw[c] = WsU[col[c]*51 + dn];
        #pragma unroll
        for (int k = 0; k < KR; k++) nx[k] = XsU[xbase + k*52 + dn];
        #pragma unroll
        for (int k = 0; k < KR; k++)
            #pragma unroll
            for (int c = 0; c < 4; c++)
                fma2(acc[k][c], x[k], w[c]);
        #pragma unroll
        for (int c = 0; c < 4; c++) w[c] = nw[c];
        #pragma unroll
        for (int k = 0; k < KR; k++) x[k] = nx[k];
    }
}

// ---------------- stage B (tf32 mma, split precision): fused gather + affine ----------------
// 128 rows/block, warp wy owns m16 tile [wy*16, wy*16+16), all 13 n8 tiles.
// Wint: interleaved (hi,lo) tf32 pairs, pitch 108 (conflict-free); Xs fp32 pitch 108.

__global__ __launch_bounds__(256) void stageBmma_k(
    const int* __restrict__ question, const int* __restrict__ q_nb,
    const int* __restrict__ s_nb, const float* __restrict__ emb_q,
    const float* __restrict__ emb_s, const float* __restrict__ aggW,
    const float* __restrict__ aggb, float* __restrict__ E2,
    float* __restrict__ E1, float* __restrict__ E0){
    extern __shared__ float sm[];
    float* Wint = sm;                 // 2*104*108 = 22464 floats (ull-interleaved hi/lo)
    float* Xs   = sm + 22464;         // 128*108   = 13824 floats
    float* bs   = Xs + 13824;         // 104
    int tid = threadIdx.x, wy = tid >> 5, lane = tid & 31;
    int bid = blockIdx.x;

    int seg, r0, R; const float* W; const float* bias; float* Y;
    if (bid < MB0)            { seg=0; r0=bid*128;            R=R2; W=aggW+20000; bias=aggb+200; Y=E2; }
    else if (bid < MB0+MB1)   { seg=1; r0=(bid-MB0)*128;      R=R1; W=aggW+10000; bias=aggb+100; Y=E1; }
    else                      { seg=2; r0=(bid-MB0-MB1)*128;  R=NN; W=aggW;       bias=aggb;     Y=E0; }

    // stage W -> (hi,lo) interleaved, zero-padded to 104x108
    for (int idx = tid; idx < 104*108; idx += 256){
        int o = idx / 108, d = idx - o*108;
        float v = (o < 100 && d < 100) ? W[o*100 + d] : 0.f;
        unsigned hi = tf32cvt(v);
        unsigned lo = tf32cvt(v - __uint_as_float(hi));
        Wint[2*idx]     = __uint_as_float(hi);
        Wint[2*idx + 1] = __uint_as_float(lo);
    }
    if (tid < 104) bs[tid] = (tid < 100) ? bias[tid] : 0.f;

    // stage X (gather), 128 rows x 108 cols fp32 (cols 100-107 zero)
    for (int rr = wy; rr < 128; rr += 8){
        if (lane < 27){
            int r = r0 + rr;
            float4 val = make_float4(0.f,0.f,0.f,0.f);
            if (lane < 25 && r < R){
                const float* basep; const int* nb; const float* tbl;
                if (seg == 0){
                    int n = r >> 4, k = (r >> 2) & 3, s = r & 3;
                    int b = n / TM, t = n - b*TM;
                    int q  = question[b*TT + t];
                    int sk = q_nb[q*4 + k];
                    int q2 = s_nb[sk*4 + s];
                    basep = emb_q + (size_t)q2*DD; nb = q_nb + q2*4; tbl = emb_s;
                } else if (seg == 1){
                    int n = r >> 2, k = r & 3;
                    int b = n / TM, t = n - b*TM;
                    int q  = question[b*TT + t];
                    int sk = q_nb[q*4 + k];
                    basep = emb_s + (size_t)sk*DD; nb = s_nb + sk*4; tbl = emb_q;
                } else {
                    int b = r / TM, t = r - b*TM;
                    int q = question[b*TT + t];
                    basep = emb_q + (size_t)q*DD; nb = q_nb + q*4; tbl = emb_s;
                }
                int i0 = nb[0], i1 = nb[1], i2 = nb[2], i3 = nb[3];
                float4 bb = ((const float4*)basep)[lane];
                float4 a = ((const float4*)(tbl + (size_t)i0*DD))[lane];
                float4 c = ((const float4*)(tbl + (size_t)i1*DD))[lane];
                float4 d = ((const float4*)(tbl + (size_t)i2*DD))[lane];
                float4 e = ((const float4*)(tbl + (size_t)i3*DD))[lane];
                val.x = bb.x + 0.25f*(a.x+c.x+d.x+e.x);
                val.y = bb.y + 0.25f*(a.y+c.y+d.y+e.y);
                val.z = bb.z + 0.25f*(a.z+c.z+d.z+e.z);
                val.w = bb.w + 0.25f*(a.w+c.w+d.w+e.w);
            }
            *(float4*)&Xs[rr*108 + 4*lane] = val;
        }
    }
    __syncthreads();

    int g = lane >> 2, tig = lane & 3;
    float acc[13][4];
    #pragma unroll
    for (int nt = 0; nt < 13; nt++)
        #pragma unroll
        for (int c = 0; c < 4; c++) acc[nt][c] = 0.f;

    const ull* WU = (const ull*)Wint;
    int xrow = wy*16 + g;
    #pragma unroll 1
    for (int k = 0; k < 13; k++){
        int k8 = k*8;
        float af0 = Xs[xrow*108       + k8 + tig];
        float af1 = Xs[(xrow+8)*108   + k8 + tig];
        float af2 = Xs[xrow*108       + k8 + tig + 4];
        float af3 = Xs[(xrow+8)*108   + k8 + tig + 4];
        unsigned ahi[4], alo[4];
        ahi[0]=tf32cvt(af0); alo[0]=tf32cvt(af0-__uint_as_float(ahi[0]));
        ahi[1]=tf32cvt(af1); alo[1]=tf32cvt(af1-__uint_as_float(ahi[1]));
        ahi[2]=tf32cvt(af2); alo[2]=tf32cvt(af2-__uint_as_float(ahi[2]));
        ahi[3]=tf32cvt(af3); alo[3]=tf32cvt(af3-__uint_as_float(ahi[3]));
        #pragma unroll
        for (int nt = 0; nt < 13; nt++){
            int wb = (nt*8 + g)*108 + k8 + tig;
            ull wv0 = WU[wb], wv1 = WU[wb + 4];
            unsigned bhi[2] = {(unsigned)wv0, (unsigned)wv1};
            unsigned blo[2] = {(unsigned)(wv0 >> 32), (unsigned)(wv1 >> 32)};
            mma_tf32(acc[nt], ahi, bhi);
            mma_tf32(acc[nt], alo, bhi);
            mma_tf32(acc[nt], ahi, blo);
        }
    }

    // epilogue: bias + tanh + store (cols 2tig,2tig+1 per n-tile; skip cols >= 100)
    int r1 = r0 + wy*16 + g;
    int r2 = r1 + 8;
    #pragma unroll
    for (int nt = 0; nt < 13; nt++){
        int c0 = nt*8 + 2*tig;
        if (c0 >= 100) continue;
        float b0 = bs[c0], b1 = bs[c0+1];
        if (r1 < R){
            float2 o; o.x = ftanh(acc[nt][0] + b0); o.y = ftanh(acc[nt][1] + b1);
            *(float2*)&Y[(size_t)r1*100 + c0] = o;
        }
        if (r2 < R){
            float2 o; o.x = ftanh(acc[nt][2] + b0); o.y = ftanh(acc[nt][3] + b1);
            *(float2*)&Y[(size_t)r2*100 + c0] = o;
        }
    }
}

// ---------------- stage C: X = base + 0.25*sum(kids), two segments (FFMA) ----------------

__global__ __launch_bounds__(256) void stageC_k(
    const float* __restrict__ E1, const float* __restrict__ E2,
    const float* __restrict__ E0a,
    const float* __restrict__ aggW, const float* __restrict__ aggb,
    float* __restrict__ E1b, float* __restrict__ E0b){
    extern __shared__ float sm[];
    float* Ws = sm;
    float* Xs = sm + 10200;
    float* bs = Xs + 48*104;
    int tid = threadIdx.x, wy = tid >> 5, lane = tid & 31;
    int bid = blockIdx.x;

    int r0, R; const float* basep; const float* kids; const float* W; const float* bias; float* Y;
    if (bid < NB1){ r0=bid*48; R=R1; basep=E1; kids=E2; W=aggW+10000; bias=aggb+100; Y=E1b; }
    else          { r0=(bid-NB1)*48; R=NN; basep=E0a; kids=E1; W=aggW; bias=aggb; Y=E0b; }

    loadW100(W, Ws, tid);
    if (tid < 100) bs[tid] = bias[tid];

    for (int rr = wy; rr < 48; rr += 8){
        if (lane < 25){
            int r = r0 + rr;
            float4 val = make_float4(0.f,0.f,0.f,0.f);
            if (r < R){
                const float4* bp = (const float4*)(basep + (size_t)r*100);
                const float4* kp = (const float4*)(kids + (size_t)r*400);
                float4 a = kp[lane], b = kp[25+lane], c = kp[50+lane], d4 = kp[75+lane];
                float4 bb = bp[lane];
                val.x = bb.x + 0.25f*(a.x+b.x+c.x+d4.x);
                val.y = bb.y + 0.25f*(a.y+b.y+c.y+d4.y);
                val.z = bb.z + 0.25f*(a.z+b.z+c.z+d4.z);
                val.w = bb.w + 0.25f*(a.w+b.w+c.w+d4.w);
            }
            *(float4*)&Xs[rr*104 + 4*lane] = val;
        }
    }
    __syncthreads();

    int c3 = (lane < 4) ? 96 + lane : 96;
    int col[4] = {lane, lane+32, lane+64, c3};
    ull acc[6][4];
    #pragma unroll
    for (int k = 0; k < 6; k++)
        #pragma unroll
        for (int c = 0; c < 4; c++) acc[k][c] = 0ull;
    core100p<6>(Ws, Xs, wy, col, acc);

    #pragma unroll
    for (int k = 0; k < 6; k++){
        int r = r0 + wy*6 + k;
        if (r >= R) continue;
        float* yo = Y + (size_t)r*100;
        yo[col[0]] = ftanh(unpack_sum(acc[k][0]) + bs[col[0]]);
        yo[col[1]] = ftanh(unpack_sum(acc[k][1]) + bs[col[1]]);
        yo[col[2]] = ftanh(unpack_sum(acc[k][2]) + bs[col[2]]);
        if (lane < 4) yo[col[3]] = ftanh(unpack_sum(acc[k][3]) + bs[col[3]]);
    }
}

// ---------------- stage D: chained double affine, 24-row tiles ----------------

__global__ __launch_bounds__(256) void stageD_k(
    const float* __restrict__ E0b, const float* __restrict__ E1b,
    const float* __restrict__ aggW, const float* __restrict__ aggb,
    const float* __restrict__ aggLW, const float* __restrict__ aggLb,
    float* __restrict__ AGG){
    extern __shared__ float sm[];
    float* Ws = sm;            // 10200
    float* Xs = sm + 10200;    // 24*104
    float* bs = Xs + 24*104;   // 100
    int tid = threadIdx.x, wy = tid >> 5, lane = tid & 31;
    int r0 = blockIdx.x * 24;

    loadW100(aggW, Ws, tid);
    if (tid < 100) bs[tid] = aggb[tid];

    for (int rr = wy; rr < 24; rr += 8){
        if (lane < 25){
            int r = r0 + rr;
            float4 val = make_float4(0.f,0.f,0.f,0.f);
            if (r < NN){
                const float4* bp = (const float4*)(E0b + (size_t)r*100);
                const float4* kp = (const float4*)(E1b + (size_t)r*400);
                float4 a = kp[lane], b = kp[25+lane], c = kp[50+lane], d4 = kp[75+lane];
                float4 bb = bp[lane];
                val.x = bb.x + 0.25f*(a.x+b.x+c.x+d4.x);
                val.y = bb.y + 0.25f*(a.y+b.y+c.y+d4.y);
                val.z = bb.z + 0.25f*(a.z+b.z+c.z+d4.z);
                val.w = bb.w + 0.25f*(a.w+b.w+c.w+d4.w);
            }
            *(float4*)&Xs[rr*104 + 4*lane] = val;
        }
    }
    __syncthreads();

    int c3 = (lane < 4) ? 96 + lane : 96;
    int col[4] = {lane, lane+32, lane+64, c3};
    ull acc[3][4];
    #pragma unroll
    for (int k = 0; k < 3; k++)
        #pragma unroll
        for (int c = 0; c < 4; c++) acc[k][c] = 0ull;
    core100p<3>(Ws, Xs, wy, col, acc);

    #pragma unroll
    for (int k = 0; k < 3; k++){
        int rr = wy*3 + k;
        int r = r0 + rr;
        if (r >= NN) continue;
        Xs[rr*104 + col[0]] = ftanh(unpack_sum(acc[k][0]) + bs[col[0]]);
        Xs[rr*104 + col[1]] = ftanh(unpack_sum(acc[k][1]) + bs[col[1]]);
        Xs[rr*104 + col[2]] = ftanh(unpack_sum(acc[k][2]) + bs[col[2]]);
        if (lane < 4) Xs[rr*104 + col[3]] = ftanh(unpack_sum(acc[k][3]) + bs[col[3]]);
    }
    __syncthreads();

    loadW100(aggLW, Ws, tid);
    if (tid < 100) bs[tid] = aggLb[tid];
    __syncthreads();

    #pragma unroll
    for (int k = 0; k < 3; k++)
        #pragma unroll
        for (int c = 0; c < 4; c++) acc[k][c] = 0ull;
    core100p<3>(Ws, Xs, wy, col, acc);

    #pragma unroll
    for (int k = 0; k < 3; k++){
        int r = r0 + wy*3 + k;
        if (r >= NN) continue;
        float* yo = AGG + (size_t)r*100;
        yo[col[0]] = ftanh(unpack_sum(acc[k][0]) + bs[col[0]]);
        yo[col[1]] = ftanh(unpack_sum(acc[k][1]) + bs[col[1]]);
        yo[col[2]] = ftanh(unpack_sum(acc[k][2]) + bs[col[2]]);
        if (lane < 4) yo[col[3]] = ftanh(unpack_sum(acc[k][3]) + bs[col[3]]);
    }
}

// ---------------- LSTM gates, column-parallel grid (199, 3); pitch 202, pipelined ----------------

__global__ __launch_bounds__(256) void gatesG_k(
    const int* __restrict__ question, const int* __restrict__ response,
    const int* __restrict__ maskp, const float* __restrict__ emb_q,
    const float* __restrict__ emb_r, const float* __restrict__ AGG,
    const float* __restrict__ Wih, const float* __restrict__ lb,
    float* __restrict__ G){
    extern __shared__ float sm[];
    float* Ws = sm;             // 100 x 202
    float* Xs = sm + 20200;     // 32 x 204
    float* bs = Xs + 32*204;    // 100
    int tid = threadIdx.x, wy = tid >> 5, lane = tid & 31;
    int ob = (blockIdx.y == 0) ? 0 : ((int)blockIdx.y + 1)*100;   // 0, 200, 300
    const float* W = Wih + (size_t)ob*200;

    for (int j = tid; j < 5000; j += 256){
        float4 v = ((const float4*)W)[j];
        int b4 = 4*j; int o = b4/200; int d = b4 - o*200;
        float2* ws = (float2*)&Ws[o*202 + d];
        ws[0] = make_float2(v.x, v.y);
        ws[1] = make_float2(v.z, v.w);
    }
    if (tid < 100) bs[tid] = lb[ob + tid];

    int r0 = blockIdx.x * 32;
    for (int rr = wy; rr < 32; rr += 8){
        if (lane < 25){
            int r = r0 + rr;
            int b = r / TM, t = r - b*TM;
            int q   = question[b*TT + t];
            int m   = maskp[b*TT + t];
            int rsp = response[b*TT + t];
            const float4* s1 = (const float4*)((m == 1) ? (AGG + (size_t)r*100)
                                                        : (emb_q + (size_t)q*100));
            const float4* s2 = (const float4*)(emb_r + (size_t)rsp*100);
            *(float4*)&Xs[rr*204 + 4*lane]       = s1[lane];
            *(float4*)&Xs[rr*204 + 100 + 4*lane] = s2[lane];
        }
    }
    __syncthreads();

    int c3 = (lane < 4) ? 96 + lane : 96;
    int col[4] = {lane, lane+32, lane+64, c3};
    ull acc[4][4];
    #pragma unroll
    for (int k = 0; k < 4; k++)
        #pragma unroll
        for (int c = 0; c < 4; c++) acc[k][c] = 0ull;

    {
        const ull* WsU = (const ull*)Ws;
        const ull* XsU = (const ull*)Xs;
        const int xbase = wy*4*102;
        ull w[4], x[4], nw[4], nx[4];
        #pragma unroll
        for (int c = 0; c < 4; c++) w[c] = WsU[col[c]*101];
        #pragma unroll
        for (int k = 0; k < 4; k++) x[k] = XsU[xbase + k*102];
        #pragma unroll 1
        for (int dw = 0; dw < 100; dw++){
            int dn = dw + 1;
            #pragma unroll
            for (int c = 0; c < 4; c++) nw[c] = WsU[col[c]*101 + dn];
            #pragma unroll
            for (int k = 0; k < 4; k++) nx[k] = XsU[xbase + k*102 + dn];
            #pragma unroll
            for (int k = 0; k < 4; k++)
                #pragma unroll
                for (int c = 0; c < 4; c++)
                    fma2(acc[k][c], x[k], w[c]);
            #pragma unroll
            for (int c = 0; c < 4; c++) w[c] = nw[c];
            #pragma unroll
            for (int k = 0; k < 4; k++) x[k] = nx[k];
        }
    }

    #pragma unroll
    for (int k = 0; k < 4; k++){
        int r = r0 + wy*4 + k;
        if (r >= NN) continue;
        float* go = G + (size_t)r*400 + ob;
        go[col[0]] = unpack_sum(acc[k][0]) + bs[col[0]];
        go[col[1]] = unpack_sum(acc[k][1]) + bs[col[1]];
        go[col[2]] = unpack_sum(acc[k][2]) + bs[col[2]];
        if (lane < 4) go[col[3]] = unpack_sum(acc[k][3]) + bs[col[3]];
    }
}

// ---------------- LSTM pointwise ----------------
__global__ void lstm_pw_k(const float* __restrict__ G, float* __restrict__ L) {
    int i = blockIdx.x*blockDim.x + threadIdx.x;
    if (i >= NN*DD) return;
    int n = i/DD, d = i - n*DD;
    const float* g = G + (size_t)n*400;
    float gi = g[d], gg = g[200+d], go = g[300+d];
    L[i] = fsig(go) * ftanh(fsig(gi) * ftanh(gg));
}

// ---------------- scores + per-t top-10 ----------------
__global__ void scores_topk_k(const int* __restrict__ question,
                              const float* __restrict__ emb_q,
                              int* __restrict__ topk) {
    extern __shared__ float sm[];
    float* P    = sm;              // [199][101]
    float* qrow = P + 199*101;     // [8][104]
    float* srow = qrow + 8*104;    // [8][200]
    int*   qidx = (int*)(srow + 8*200);  // [200]
    int b = blockIdx.x;
    int tid = threadIdx.x, w = tid >> 5, lane = tid & 31;
    if (tid < TT) qidx[tid] = question[b*TT + tid];
    __syncthreads();
    int tmax = min(TM - 1, (int)blockIdx.y*8 + 7);
    int rmax = tmax;
    for (int i = tid; i < rmax*DD; i += 256) {
        int s = i / DD, d = i - s*DD;
        P[s*101 + d] = emb_q[(size_t)qidx[s]*DD + d];
    }
    __syncthreads();
    int t = blockIdx.y*8 + w;
    if (t >= TM) return;
    int qv = qidx[t + 1];
    for (int d = lane; d < DD; d += 32) qrow[w*104 + d] = emb_q[(size_t)qv*DD + d];
    __syncwarp();
    for (int s = lane; s < t; s += 32) {
        float acc = 0.f;
        const float* pr = P + s*101;
        const float* qr = qrow + w*104;
        #pragma unroll 4
        for (int d = 0; d < DD; d++) acc += qr[d]*pr[d];
        srow[w*200 + s] = acc;
    }
    __syncwarp();
    int n = b*TM + t;
    int cnt = min(t, KK);
    for (int sel = 0; sel < KK; sel++) {
        if (sel < cnt) {
            float bv = -3.4e38f; unsigned bi = 0xffffffffu;
            for (int s = lane; s < t; s += 32) {
                float v = srow[w*200 + s];
                if (v > bv) { bv = v; bi = (unsigned)s; }
            }
            #pragma unroll
            for (int off = 16; off; off >>= 1) {
                float    ov = __shfl_down_sync(0xffffffffu, bv, off);
                unsigned oi = __shfl_down_sync(0xffffffffu, bi, off);
                if (ov > bv || (ov == bv && oi < bi)) { bv = ov; bi = oi; }
            }
            bi = __shfl_sync(0xffffffffu, bi, 0);
            if (lane == 0) { topk[n*KK + sel] = (int)bi; srow[w*200 + bi] = -3.4e38f; }
            __syncwarp();
        } else if (lane == 0) {
            topk[n*KK + sel] = -1;
        }
    }
}

// ---------------- fused KT affine + attention + output ----------------

__global__ __launch_bounds__(256) void ktfinal_k(
    const int* __restrict__ question, const int* __restrict__ skidx,
    const int* __restrict__ skmask, const float* __restrict__ emb_q,
    const float* __restrict__ emb_s, const float* __restrict__ L,
    const int* __restrict__ topk, const float* __restrict__ Wq,
    const float* __restrict__ bq, const float* __restrict__ w_att,
    float* __restrict__ out){
    extern __shared__ float sm[];
    float* Ws  = sm;               // 10200
    float* Xs  = sm + 10200;       // 48*104
    float* bs  = Xs + 48*104;      // 100
    float* w2s = bs + 100;         // 100
    float* qsm = w2s + 100;        // 4*104
    float* ktm = qsm + 4*104;      // 48
    float* gvm = ktm + 48;         // 48
    int tid = threadIdx.x, wy = tid >> 5, lane = tid & 31;
    int n0 = blockIdx.x * 4;

    loadW100(Wq, Ws, tid);
    if (tid < 100) { bs[tid] = bq[tid]; w2s[tid] = w_att[100 + tid]; }

    for (int rr = wy; rr < 48; rr += 8){
        if (lane < 25){
            float4 val = make_float4(0.f,0.f,0.f,0.f);
            if (rr < 44){
                int n = n0 + rr/11, s = rr - (rr/11)*11;
                int b = n / TM, t = n - b*TM;
                int cnt = min(t, KK);
                const float* src = nullptr;
                if (s == 0) src = L + (size_t)n*100;
                else if (s-1 < cnt){
                    int idx = topk[n*KK + s - 1];
                    if (idx > 0) src = L + ((size_t)b*TM + idx)*100;
                }
                if (src) val = ((const float4*)src)[lane];
            }
            *(float4*)&Xs[rr*104 + 4*lane] = val;
        }
    }
    if (wy < 4){
        int n = n0 + wy;
        int b = n / TM, t = n - b*TM;
        int qv = question[b*TT + t + 1];
        if (lane < 25){
            float4 v = ((const float4*)(emb_q + (size_t)qv*100))[lane];
            #pragma unroll
            for (int i = 0; i < 4; i++){
                if (skmask[qv*4 + i] != 0){
                    float4 e = ((const float4*)(emb_s + (size_t)skidx[qv*4 + i]*100))[lane];
                    v.x += e.x; v.y += e.y; v.z += e.z; v.w += e.w;
                }
            }
            *(float4*)&qsm[wy*104 + 4*lane] = v;
        }
    }
    __syncthreads();

    int c3 = (lane < 4) ? 96 + lane : 96;
    int col[4] = {lane, lane+32, lane+64, c3};
    ull acc[6][4];
    #pragma unroll
    for (int k = 0; k < 6; k++)
        #pragma unroll
        for (int c = 0; c < 4; c++) acc[k][c] = 0ull;
    core100p<6>(Ws, Xs, wy, col, acc);

    #pragma unroll
    for (int k = 0; k < 6; k++){
        int rr = wy*6 + k;
        if (rr >= 44) continue;
        int nl = rr / 11;
        float o0 = ftanh(unpack_sum(acc[k][0]) + bs[col[0]]);
        float o1 = ftanh(unpack_sum(acc[k][1]) + bs[col[1]]);
        float o2 = ftanh(unpack_sum(acc[k][2]) + bs[col[2]]);
        float o3 = ftanh(unpack_sum(acc[k][3]) + bs[col[3]]);
        float v = o0*w2s[col[0]] + o1*w2s[col[1]] + o2*w2s[col[2]];
        float g = Xs[rr*104+col[0]]*qsm[nl*104+col[0]]
                + Xs[rr*104+col[1]]*qsm[nl*104+col[1]]
                + Xs[rr*104+col[2]]*qsm[nl*104+col[2]];
        if (lane < 4){
            v += o3*w2s[col[3]];
            g += Xs[rr*104+col[3]]*qsm[nl*104+col[3]];
        }
        #pragma unroll
        for (int off = 16; off; off >>= 1){
            v += __shfl_down_sync(0xffffffffu, v, off);
            g += __shfl_down_sync(0xffffffffu, g, off);
        }
        if (lane == 0){ ktm[rr] = v; gvm[rr] = g; }
    }
    __syncthreads();

    if (tid < 4){
        int n = n0 + tid;
        int b = n / TM, t = n - b*TM;
        int cnt = min(t, KK);
        float m = -3.4e38f;
        for (int s = 0; s <= cnt; s++){ float v = ktm[tid*11 + s]; if (v > m) m = v; }
        float Z = 0.f, P = 0.f;
        for (int s = 0; s <= cnt; s++){
            float e = __expf(ktm[tid*11 + s] - m);
            Z += e; P += e*gvm[tid*11 + s];
        }
        out[b*TT + 1 + t] = fsig(__fdividef(P, Z));
    }
}

__global__ void tail_k(const float* __restrict__ L, float* __restrict__ out) {
    int i = blockIdx.x*blockDim.x + threadIdx.x;
    if (i < BB) out[i*TT] = 0.5f;
    if (i < BB*DD) {
        int b = i / DD;
        out[BB*TT + i] = L[((size_t)b*TM + (TM-1))*DD + (i - b*DD)];
    }
}

// ---------------- launch ----------------

extern "C" void kernel_launch(void* const* d_in, const int* in_sizes, int n_in,
                              void* d_out, int out_size) {
    const int*   question = (const int*)d_in[0];
    const int*   response = (const int*)d_in[1];
    const int*   maskp    = (const int*)d_in[2];
    const int*   q_nb     = (const int*)d_in[3];
    const int*   s_nb     = (const int*)d_in[4];
    const int*   skidx    = (const int*)d_in[5];
    const int*   skmask   = (const int*)d_in[6];
    const float* emb_q    = (const float*)d_in[7];
    const float* emb_s    = (const float*)d_in[8];
    const float* emb_r    = (const float*)d_in[9];
    const float* Wih      = (const float*)d_in[10];
    const float* lb       = (const float*)d_in[11];
    const float* aggW     = (const float*)d_in[12];
    const float* aggb     = (const float*)d_in[13];
    const float* aggLW    = (const float*)d_in[14];
    const float* aggLb    = (const float*)d_in[15];
    const float* Wq       = (const float*)d_in[16];
    const float* bq       = (const float*)d_in[17];
    const float* w_att    = (const float*)d_in[20];
    float* out = (float*)d_out;

    float* buf = nullptr; int* topk = nullptr;
    cudaGetSymbolAddress((void**)&buf,  g_buf);
    cudaGetSymbolAddress((void**)&topk, g_topk);

    float* pE2  = buf + OFF_E2;
    float* pE1  = buf + OFF_E1;
    float* pE0a = buf + OFF_E0A;
    float* pE1b = buf + OFF_E1B;
    float* pE0b = buf + OFF_E0B;
    float* pAGG = buf + OFF_AGG;
    float* pL   = buf + OFF_L;
    float* pG   = buf + OFF_G;

    const int BMM_SMEM = (22464 + 13824 + 104)*4;   // 145568
    const int AFF_SMEM = (10200 + 48*104 + 100)*4;
    const int D_SMEM   = (10200 + 24*104 + 100)*4;
    const int KTF_SMEM = (10200 + 48*104 + 100 + 100 + 4*104 + 48 + 48)*4;
    const int GAT_SMEM = (20200 + 32*204 + 100)*4;
    const int SCO_SMEM = (199*101 + 8*104 + 8*200)*4 + 200*4;
    cudaFuncSetAttribute(stageBmma_k,   cudaFuncAttributeMaxDynamicSharedMemorySize, BMM_SMEM);
    cudaFuncSetAttribute(stageC_k,      cudaFuncAttributeMaxDynamicSharedMemorySize, AFF_SMEM);
    cudaFuncSetAttribute(stageD_k,      cudaFuncAttributeMaxDynamicSharedMemorySize, D_SMEM);
    cudaFuncSetAttribute(gatesG_k,      cudaFuncAttributeMaxDynamicSharedMemorySize, GAT_SMEM);
    cudaFuncSetAttribute(scores_topk_k, cudaFuncAttributeMaxDynamicSharedMemorySize, SCO_SMEM);
    cudaFuncSetAttribute(ktfinal_k,     cudaFuncAttributeMaxDynamicSharedMemorySize, KTF_SMEM);

    scores_topk_k<<<dim3(BB, 25), 256, SCO_SMEM>>>(question, emb_q, topk);

    stageBmma_k<<<MB0+MB1+MB2, 256, BMM_SMEM>>>(question, q_nb, s_nb, emb_q, emb_s,
                                                aggW, aggb, pE2, pE1, pE0a);
    stageC_k<<<NB1+NB2, 256, AFF_SMEM>>>(pE1, pE2, pE0a, aggW, aggb, pE1b, pE0b);
    stageD_k<<<NBD, 256, D_SMEM>>>(pE0b, pE1b, aggW, aggb, aggLW, aggLb, pAGG);

    gatesG_k<<<dim3(NN/32, 3), 256, GAT_SMEM>>>(question, response, maskp, emb_q, emb_r,
                                                pAGG, Wih, lb, pG);
    lstm_pw_k<<<(NN*DD + 255)/256, 256>>>(pG, pL);

    ktfinal_k<<<NN/4, 256, KTF_SMEM>>>(question, skidx, skmask, emb_q, emb_s,
                                       pL, topk, Wq, bq, w_att, out);
    tail_k<<<(BB*DD + 255)/256, 256>>>(pL, out);
}

// round 11
// speedup vs baseline: 1.1684x; 1.1684x over previous
#include <cuda_runtime.h>
#include <math.h>

#define BB 32
#define TT 200
#define TM 199
#define NN (BB*TM)        // 6368
#define DD 100
#define KK 10
#define R2 (NN*16)        // 101888
#define R1 (NN*4)        // 25472

#define NB0 2123          // ceil(R2/48)
#define NB1 531           // ceil(R1/48)
#define NB2 133           // ceil(NN/48)
#define NBD 266           // ceil(NN/24)

typedef unsigned long long ull;

// ---------------- scratch ----------------
__device__ float g_buf[20377600];
__device__ int   g_topk[NN*KK];

static constexpr size_t OFF_E2  = 0;          // R2*100
static constexpr size_t OFF_E1  = 10188800;   // R1*100
static constexpr size_t OFF_E0A = 12736000;   // NN*100
static constexpr size_t OFF_E1B = 13372800;   // R1*100
static constexpr size_t OFF_E0B = 15920000;   // NN*100
static constexpr size_t OFF_AGG = 16556800;   // NN*100
static constexpr size_t OFF_L   = 17193600;   // NN*100
static constexpr size_t OFF_G   = 17830400;   // NN*400

// ---------------- helpers ----------------
__device__ __forceinline__ void fma2(ull& a, ull x, ull w){
    asm("fma.rn.f32x2 %0, %1, %2, %0;" : "+l"(a) : "l"(x), "l"(w));
}
__device__ __forceinline__ float unpack_sum(ull a){
    float lo = __int_as_float((int)(unsigned int)a);
    float hi = __int_as_float((int)(unsigned int)(a >> 32));
    return lo + hi;
}
__device__ __forceinline__ float ftanh(float x){
    float e = __expf(2.f*x);
    return 1.f - __fdividef(2.f, e + 1.f);
}
__device__ __forceinline__ float fsig(float x){
    return __fdividef(1.f, 1.f + __expf(-x));
}

// load 100x100 W into smem pitch 102 (51 ull words; conflict-free LDS.64)
__device__ __forceinline__ void loadW100(const float* __restrict__ W, float* Ws, int tid){
    for (int j = tid; j < 2500; j += 256){
        float4 v = ((const float4*)W)[j];
        int b4 = 4*j; int o = b4/100; int d = b4 - o*100;
        float2* ws = (float2*)&Ws[o*102 + d];
        ws[0] = make_float2(v.x, v.y);
        ws[1] = make_float2(v.z, v.w);
    }
}

// Software-pipelined KR-rows-per-thread 100-d FFMA core.
template<int KR>
__device__ __forceinline__ void core100p(const float* Ws, const float* Xs, int wy,
                                         const int* col, ull (*acc)[4]){
    const ull* WsU = (const ull*)Ws;
    const ull* XsU = (const ull*)Xs;
    const int xbase = wy*KR*52;
    ull w[4], x[KR], nw[4], nx[KR];
    #pragma unroll
    for (int c = 0; c < 4; c++) w[c] = WsU[col[c]*51];
    #pragma unroll
    for (int k = 0; k < KR; k++) x[k] = XsU[xbase + k*52];
    #pragma unroll 1
    for (int dw = 0; dw < 50; dw++){
        int dn = dw + 1;
        #pragma unroll
        for (int c = 0; c < 4; c++) nw[c] = WsU[col[c]*51 + dn];
        #pragma unroll
        for (int k = 0; k < KR; k++) nx[k] = XsU[xbase + k*52 + dn];
        #pragma unroll
        for (int k = 0; k < KR; k++)
            #pragma unroll
            for (int c = 0; c < 4; c++)
                fma2(acc[k][c], x[k], w[c]);
        #pragma unroll
        for (int c = 0; c < 4; c++) w[c] = nw[c];
        #pragma unroll
        for (int k = 0; k < KR; k++) x[k] = nx[k];
    }
}

// ---------------- stage B: fused gather + affine, 3 segments in one grid ----------------

__global__ __launch_bounds__(256) void stageB_k(
    const int* __restrict__ question, const int* __restrict__ q_nb,
    const int* __restrict__ s_nb, const float* __restrict__ emb_q,
    const float* __restrict__ emb_s, const float* __restrict__ aggW,
    const float* __restrict__ aggb, float* __restrict__ E2,
    float* __restrict__ E1, float* __restrict__ E0){
    extern __shared__ float sm[];
    float* Ws = sm;            // 10200
    float* Xs = sm + 10200;    // 48*104
    float* bs = Xs + 48*104;   // 100
    int tid = threadIdx.x, wy = tid >> 5, lane = tid & 31;
    int bid = blockIdx.x;

    int seg, r0, R; const float* W; const float* bias; float* Y;
    if (bid < NB0)            { seg=0; r0=bid*48;            R=R2; W=aggW+20000; bias=aggb+200; Y=E2; }
    else if (bid < NB0+NB1)   { seg=1; r0=(bid-NB0)*48;      R=R1; W=aggW+10000; bias=aggb+100; Y=E1; }
    else                      { seg=2; r0=(bid-NB0-NB1)*48;  R=NN; W=aggW;       bias=aggb;     Y=E0; }

    loadW100(W, Ws, tid);
    if (tid < 100) bs[tid] = bias[tid];

    for (int rr = wy; rr < 48; rr += 8){
        if (lane < 25){
            int r = r0 + rr;
            float4 val = make_float4(0.f,0.f,0.f,0.f);
            if (r < R){
                const float* basep; const int* nb; const float* tbl;
                if (seg == 0){
                    int n = r >> 4, k = (r >> 2) & 3, s = r & 3;
                    int b = n / TM, t = n - b*TM;
                    int q  = question[b*TT + t];
                    int sk = q_nb[q*4 + k];
                    int q2 = s_nb[sk*4 + s];
                    basep = emb_q + (size_t)q2*DD; nb = q_nb + q2*4; tbl = emb_s;
                } else if (seg == 1){
                    int n = r >> 2, k = r & 3;
                    int b = n / TM, t = n - b*TM;
                    int q  = question[b*TT + t];
                    int sk = q_nb[q*4 + k];
                    basep = emb_s + (size_t)sk*DD; nb = s_nb + sk*4; tbl = emb_q;
                } else {
                    int b = r / TM, t = r - b*TM;
                    int q = question[b*TT + t];
                    basep = emb_q + (size_t)q*DD; nb = q_nb + q*4; tbl = emb_s;
                }
                int i0 = nb[0], i1 = nb[1], i2 = nb[2], i3 = nb[3];
                float4 bb = ((const float4*)basep)[lane];
                float4 a = ((const float4*)(tbl + (size_t)i0*DD))[lane];
                float4 c = ((const float4*)(tbl + (size_t)i1*DD))[lane];
                float4 d = ((const float4*)(tbl + (size_t)i2*DD))[lane];
                float4 e = ((const float4*)(tbl + (size_t)i3*DD))[lane];
                val.x = bb.x + 0.25f*(a.x+c.x+d.x+e.x);
                val.y = bb.y + 0.25f*(a.y+c.y+d.y+e.y);
                val.z = bb.z + 0.25f*(a.z+c.z+d.z+e.z);
                val.w = bb.w + 0.25f*(a.w+c.w+d.w+e.w);
            }
            *(float4*)&Xs[rr*104 + 4*lane] = val;
        }
    }
    __syncthreads();

    int c3 = (lane < 4) ? 96 + lane : 96;
    int col[4] = {lane, lane+32, lane+64, c3};
    ull acc[6][4];
    #pragma unroll
    for (int k = 0; k < 6; k++)
        #pragma unroll
        for (int c = 0; c < 4; c++) acc[k][c] = 0ull;
    core100p<6>(Ws, Xs, wy, col, acc);

    #pragma unroll
    for (int k = 0; k < 6; k++){
        int r = r0 + wy*6 + k;
        if (r >= R) continue;
        float* yo = Y + (size_t)r*100;
        yo[col[0]] = ftanh(unpack_sum(acc[k][0]) + bs[col[0]]);
        yo[col[1]] = ftanh(unpack_sum(acc[k][1]) + bs[col[1]]);
        yo[col[2]] = ftanh(unpack_sum(acc[k][2]) + bs[col[2]]);
        if (lane < 4) yo[col[3]] = ftanh(unpack_sum(acc[k][3]) + bs[col[3]]);
    }
}

// ---------------- stage C: X = base + 0.25*sum(kids), two segments ----------------

__global__ __launch_bounds__(256) void stageC_k(
    const float* __restrict__ E1, const float* __restrict__ E2,
    const float* __restrict__ E0a,
    const float* __restrict__ aggW, const float* __restrict__ aggb,
    float* __restrict__ E1b, float* __restrict__ E0b){
    extern __shared__ float sm[];
    float* Ws = sm;
    float* Xs = sm + 10200;
    float* bs = Xs + 48*104;
    int tid = threadIdx.x, wy = tid >> 5, lane = tid & 31;
    int bid = blockIdx.x;

    int r0, R; const float* basep; const float* kids; const float* W; const float* bias; float* Y;
    if (bid < NB1){ r0=bid*48; R=R1; basep=E1; kids=E2; W=aggW+10000; bias=aggb+100; Y=E1b; }
    else          { r0=(bid-NB1)*48; R=NN; basep=E0a; kids=E1; W=aggW; bias=aggb; Y=E0b; }

    loadW100(W, Ws, tid);
    if (tid < 100) bs[tid] = bias[tid];

    for (int rr = wy; rr < 48; rr += 8){
        if (lane < 25){
            int r = r0 + rr;
            float4 val = make_float4(0.f,0.f,0.f,0.f);
            if (r < R){
                const float4* bp = (const float4*)(basep + (size_t)r*100);
                const float4* kp = (const float4*)(kids + (size_t)r*400);
                float4 a = kp[lane], b = kp[25+lane], c = kp[50+lane], d4 = kp[75+lane];
                float4 bb = bp[lane];
                val.x = bb.x + 0.25f*(a.x+b.x+c.x+d4.x);
                val.y = bb.y + 0.25f*(a.y+b.y+c.y+d4.y);
                val.z = bb.z + 0.25f*(a.z+b.z+c.z+d4.z);
                val.w = bb.w + 0.25f*(a.w+b.w+c.w+d4.w);
            }
            *(float4*)&Xs[rr*104 + 4*lane] = val;
        }
    }
    __syncthreads();

    int c3 = (lane < 4) ? 96 + lane : 96;
    int col[4] = {lane, lane+32, lane+64, c3};
    ull acc[6][4];
    #pragma unroll
    for (int k = 0; k < 6; k++)
        #pragma unroll
        for (int c = 0; c < 4; c++) acc[k][c] = 0ull;
    core100p<6>(Ws, Xs, wy, col, acc);

    #pragma unroll
    for (int k = 0; k < 6; k++){
        int r = r0 + wy*6 + k;
        if (r >= R) continue;
        float* yo = Y + (size_t)r*100;
        yo[col[0]] = ftanh(unpack_sum(acc[k][0]) + bs[col[0]]);
        yo[col[1]] = ftanh(unpack_sum(acc[k][1]) + bs[col[1]]);
        yo[col[2]] = ftanh(unpack_sum(acc[k][2]) + bs[col[2]]);
        if (lane < 4) yo[col[3]] = ftanh(unpack_sum(acc[k][3]) + bs[col[3]]);
    }
}

// ---------------- stage D: chained double affine, 24-row tiles (grid 266) ----------------

__global__ __launch_bounds__(256) void stageD_k(
    const float* __restrict__ E0b, const float* __restrict__ E1b,
    const float* __restrict__ aggW, const float* __restrict__ aggb,
    const float* __restrict__ aggLW, const float* __restrict__ aggLb,
    float* __restrict__ AGG){
    extern __shared__ float sm[];
    float* Ws = sm;            // 10200
    float* Xs = sm + 10200;    // 24*104
    float* bs = Xs + 24*104;   // 100
    int tid = threadIdx.x, wy = tid >> 5, lane = tid & 31;
    int r0 = blockIdx.x * 24;

    loadW100(aggW, Ws, tid);
    if (tid < 100) bs[tid] = aggb[tid];

    for (int rr = wy; rr < 24; rr += 8){
        if (lane < 25){
            int r = r0 + rr;
            float4 val = make_float4(0.f,0.f,0.f,0.f);
            if (r < NN){
                const float4* bp = (const float4*)(E0b + (size_t)r*100);
                const float4* kp = (const float4*)(E1b + (size_t)r*400);
                float4 a = kp[lane], b = kp[25+lane], c = kp[50+lane], d4 = kp[75+lane];
                float4 bb = bp[lane];
                val.x = bb.x + 0.25f*(a.x+b.x+c.x+d4.x);
                val.y = bb.y + 0.25f*(a.y+b.y+c.y+d4.y);
                val.z = bb.z + 0.25f*(a.z+b.z+c.z+d4.z);
                val.w = bb.w + 0.25f*(a.w+b.w+c.w+d4.w);
            }
            *(float4*)&Xs[rr*104 + 4*lane] = val;
        }
    }
    __syncthreads();

    int c3 = (lane < 4) ? 96 + lane : 96;
    int col[4] = {lane, lane+32, lane+64, c3};
    ull acc[3][4];
    #pragma unroll
    for (int k = 0; k < 3; k++)
        #pragma unroll
        for (int c = 0; c < 4; c++) acc[k][c] = 0ull;
    core100p<3>(Ws, Xs, wy, col, acc);

    #pragma unroll
    for (int k = 0; k < 3; k++){
        int rr = wy*3 + k;
        int r = r0 + rr;
        if (r >= NN) continue;
        Xs[rr*104 + col[0]] = ftanh(unpack_sum(acc[k][0]) + bs[col[0]]);
        Xs[rr*104 + col[1]] = ftanh(unpack_sum(acc[k][1]) + bs[col[1]]);
        Xs[rr*104 + col[2]] = ftanh(unpack_sum(acc[k][2]) + bs[col[2]]);
        if (lane < 4) Xs[rr*104 + col[3]] = ftanh(unpack_sum(acc[k][3]) + bs[col[3]]);
    }
    __syncthreads();

    loadW100(aggLW, Ws, tid);
    if (tid < 100) bs[tid] = aggLb[tid];
    __syncthreads();

    #pragma unroll
    for (int k = 0; k < 3; k++)
        #pragma unroll
        for (int c = 0; c < 4; c++) acc[k][c] = 0ull;
    core100p<3>(Ws, Xs, wy, col, acc);

    #pragma unroll
    for (int k = 0; k < 3; k++){
        int r = r0 + wy*3 + k;
        if (r >= NN) continue;
        float* yo = AGG + (size_t)r*100;
        yo[col[0]] = ftanh(unpack_sum(acc[k][0]) + bs[col[0]]);
        yo[col[1]] = ftanh(unpack_sum(acc[k][1]) + bs[col[1]]);
        yo[col[2]] = ftanh(unpack_sum(acc[k][2]) + bs[col[2]]);
        if (lane < 4) yo[col[3]] = ftanh(unpack_sum(acc[k][3]) + bs[col[3]]);
    }
}

// ---------------- LSTM gates, column-parallel grid (199, 3); pitch 202, pipelined ----------------

__global__ __launch_bounds__(256) void gatesG_k(
    const int* __restrict__ question, const int* __restrict__ response,
    const int* __restrict__ maskp, const float* __restrict__ emb_q,
    const float* __restrict__ emb_r, const float* __restrict__ AGG,
    const float* __restrict__ Wih, const float* __restrict__ lb,
    float* __restrict__ G){
    extern __shared__ float sm[];
    float* Ws = sm;             // 100 x 202
    float* Xs = sm + 20200;     // 32 x 204
    float* bs = Xs + 32*204;    // 100
    int tid = threadIdx.x, wy = tid >> 5, lane = tid & 31;
    int ob = (blockIdx.y == 0) ? 0 : ((int)blockIdx.y + 1)*100;   // 0, 200, 300
    const float* W = Wih + (size_t)ob*200;

    for (int j = tid; j < 5000; j += 256){
        float4 v = ((const float4*)W)[j];
        int b4 = 4*j; int o = b4/200; int d = b4 - o*200;
        float2* ws = (float2*)&Ws[o*202 + d];
        ws[0] = make_float2(v.x, v.y);
        ws[1] = make_float2(v.z, v.w);
    }
    if (tid < 100) bs[tid] = lb[ob + tid];

    int r0 = blockIdx.x * 32;
    for (int rr = wy; rr < 32; rr += 8){
        if (lane < 25){
            int r = r0 + rr;
            int b = r / TM, t = r - b*TM;
            int q   = question[b*TT + t];
            int m   = maskp[b*TT + t];
            int rsp = response[b*TT + t];
            const float4* s1 = (const float4*)((m == 1) ? (AGG + (size_t)r*100)
                                                        : (emb_q + (size_t)q*100));
            const float4* s2 = (const float4*)(emb_r + (size_t)rsp*100);
            *(float4*)&Xs[rr*204 + 4*lane]       = s1[lane];
            *(float4*)&Xs[rr*204 + 100 + 4*lane] = s2[lane];
        }
    }
    __syncthreads();

    int c3 = (lane < 4) ? 96 + lane : 96;
    int col[4] = {lane, lane+32, lane+64, c3};
    ull acc[4][4];
    #pragma unroll
    for (int k = 0; k < 4; k++)
        #pragma unroll
        for (int c = 0; c < 4; c++) acc[k][c] = 0ull;

    {
        const ull* WsU = (const ull*)Ws;
        const ull* XsU = (const ull*)Xs;
        const int xbase = wy*4*102;
        ull w[4], x[4], nw[4], nx[4];
        #pragma unroll
        for (int c = 0; c < 4; c++) w[c] = WsU[col[c]*101];
        #pragma unroll
        for (int k = 0; k < 4; k++) x[k] = XsU[xbase + k*102];
        #pragma unroll 1
        for (int dw = 0; dw < 100; dw++){
            int dn = dw + 1;
            #pragma unroll
            for (int c = 0; c < 4; c++) nw[c] = WsU[col[c]*101 + dn];
            #pragma unroll
            for (int k = 0; k < 4; k++) nx[k] = XsU[xbase + k*102 + dn];
            #pragma unroll
            for (int k = 0; k < 4; k++)
                #pragma unroll
                for (int c = 0; c < 4; c++)
                    fma2(acc[k][c], x[k], w[c]);
            #pragma unroll
            for (int c = 0; c < 4; c++) w[c] = nw[c];
            #pragma unroll
            for (int k = 0; k < 4; k++) x[k] = nx[k];
        }
    }

    #pragma unroll
    for (int k = 0; k < 4; k++){
        int r = r0 + wy*4 + k;
        if (r >= NN) continue;
        float* go = G + (size_t)r*400 + ob;
        go[col[0]] = unpack_sum(acc[k][0]) + bs[col[0]];
        go[col[1]] = unpack_sum(acc[k][1]) + bs[col[1]];
        go[col[2]] = unpack_sum(acc[k][2]) + bs[col[2]];
        if (lane < 4) go[col[3]] = unpack_sum(acc[k][3]) + bs[col[3]];
    }
}

// ---------------- LSTM pointwise ----------------
__global__ void lstm_pw_k(const float* __restrict__ G, float* __restrict__ L) {
    int i = blockIdx.x*blockDim.x + threadIdx.x;
    if (i >= NN*DD) return;
    int n = i/DD, d = i - n*DD;
    const float* g = G + (size_t)n*400;
    float gi = g[d], gg = g[200+d], go = g[300+d];
    L[i] = fsig(go) * ftanh(fsig(gi) * ftanh(gg));
}

// ---------------- scores + per-t top-10 ----------------
__global__ void scores_topk_k(const int* __restrict__ question,
                              const float* __restrict__ emb_q,
                              int* __restrict__ topk) {
    extern __shared__ float sm[];
    float* P    = sm;              // [199][101]
    float* qrow = P + 199*101;     // [8][104]
    float* srow = qrow + 8*104;    // [8][200]
    int*   qidx = (int*)(srow + 8*200);  // [200]
    int b = blockIdx.x;
    int tid = threadIdx.x, w = tid >> 5, lane = tid & 31;
    if (tid < TT) qidx[tid] = question[b*TT + tid];
    __syncthreads();
    int tmax = min(TM - 1, (int)blockIdx.y*8 + 7);
    int rmax = tmax;
    for (int i = tid; i < rmax*DD; i += 256) {
        int s = i / DD, d = i - s*DD;
        P[s*101 + d] = emb_q[(size_t)qidx[s]*DD + d];
    }
    __syncthreads();
    int t = blockIdx.y*8 + w;
    if (t >= TM) return;
    int qv = qidx[t + 1];
    for (int d = lane; d < DD; d += 32) qrow[w*104 + d] = emb_q[(size_t)qv*DD + d];
    __syncwarp();
    for (int s = lane; s < t; s += 32) {
        float acc = 0.f;
        const float* pr = P + s*101;
        const float* qr = qrow + w*104;
        #pragma unroll 4
        for (int d = 0; d < DD; d++) acc += qr[d]*pr[d];
        srow[w*200 + s] = acc;
    }
    __syncwarp();
    int n = b*TM + t;
    int cnt = min(t, KK);
    for (int sel = 0; sel < KK; sel++) {
        if (sel < cnt) {
            float bv = -3.4e38f; unsigned bi = 0xffffffffu;
            for (int s = lane; s < t; s += 32) {
                float v = srow[w*200 + s];
                if (v > bv) { bv = v; bi = (unsigned)s; }
            }
            #pragma unroll
            for (int off = 16; off; off >>= 1) {
                float    ov = __shfl_down_sync(0xffffffffu, bv, off);
                unsigned oi = __shfl_down_sync(0xffffffffu, bi, off);
                if (ov > bv || (ov == bv && oi < bi)) { bv = ov; bi = oi; }
            }
            bi = __shfl_sync(0xffffffffu, bi, 0);
            if (lane == 0) { topk[n*KK + sel] = (int)bi; srow[w*200 + bi] = -3.4e38f; }
            __syncwarp();
        } else if (lane == 0) {
            topk[n*KK + sel] = -1;
        }
    }
}

// ---------------- fused KT affine + attention + output: 8 n's (88 hist rows), 2-pass W reuse ----------------

__global__ __launch_bounds__(256) void ktfinal_k(
    const int* __restrict__ question, const int* __restrict__ skidx,
    const int* __restrict__ skmask, const float* __restrict__ emb_q,
    const float* __restrict__ emb_s, const float* __restrict__ L,
    const int* __restrict__ topk, const float* __restrict__ Wq,
    const float* __restrict__ bq, const float* __restrict__ w_att,
    float* __restrict__ out){
    extern __shared__ float sm[];
    float* Ws  = sm;               // 10200
    float* Xs  = sm + 10200;       // 96*104
    float* bs  = Xs + 96*104;      // 100
    float* w2s = bs + 100;         // 100
    float* qsm = w2s + 100;        // 8*104
    float* ktm = qsm + 8*104;      // 96
    float* gvm = ktm + 96;         // 96
    int tid = threadIdx.x, wy = tid >> 5, lane = tid & 31;
    int n0 = blockIdx.x * 8;

    loadW100(Wq, Ws, tid);
    if (tid < 100) { bs[tid] = bq[tid]; w2s[tid] = w_att[100 + tid]; }

    // hist rows (88 real, 8 pad)
    for (int rr = wy; rr < 96; rr += 8){
        if (lane < 25){
            float4 val = make_float4(0.f,0.f,0.f,0.f);
            if (rr < 88){
                int n = n0 + rr/11, s = rr - (rr/11)*11;
                int b = n / TM, t = n - b*TM;
                int cnt = min(t, KK);
                const float* src = nullptr;
                if (s == 0) src = L + (size_t)n*100;
                else if (s-1 < cnt){
                    int idx = topk[n*KK + s - 1];
                    if (idx > 0) src = L + ((size_t)b*TM + idx)*100;
                }
                if (src) val = ((const float4*)src)[lane];
            }
            *(float4*)&Xs[rr*104 + 4*lane] = val;
        }
    }
    // qs rows (skill-augmented query), one warp per n (all 8 warps)
    {
        int n = n0 + wy;
        int b = n / TM, t = n - b*TM;
        int qv = question[b*TT + t + 1];
        if (lane < 25){
            float4 v = ((const float4*)(emb_q + (size_t)qv*100))[lane];
            #pragma unroll
            for (int i = 0; i < 4; i++){
                if (skmask[qv*4 + i] != 0){
                    float4 e = ((const float4*)(emb_s + (size_t)skidx[qv*4 + i]*100))[lane];
                    v.x += e.x; v.y += e.y; v.z += e.z; v.w += e.w;
                }
            }
            *(float4*)&qsm[wy*104 + 4*lane] = v;
        }
    }
    __syncthreads();

    int c3 = (lane < 4) ? 96 + lane : 96;
    int col[4] = {lane, lane+32, lane+64, c3};

    #pragma unroll 1
    for (int p = 0; p < 2; p++){
        ull acc[6][4];
        #pragma unroll
        for (int k = 0; k < 6; k++)
            #pragma unroll
            for (int c = 0; c < 4; c++) acc[k][c] = 0ull;
        core100p<6>(Ws, Xs + p*48*104, wy, col, acc);

        #pragma unroll
        for (int k = 0; k < 6; k++){
            int gr = p*48 + wy*6 + k;
            if (gr >= 88) continue;
            int nl = gr / 11;
            float o0 = ftanh(unpack_sum(acc[k][0]) + bs[col[0]]);
            float o1 = ftanh(unpack_sum(acc[k][1]) + bs[col[1]]);
            float o2 = ftanh(unpack_sum(acc[k][2]) + bs[col[2]]);
            float o3 = ftanh(unpack_sum(acc[k][3]) + bs[col[3]]);
            float v = o0*w2s[col[0]] + o1*w2s[col[1]] + o2*w2s[col[2]];
            float g = Xs[gr*104+col[0]]*qsm[nl*104+col[0]]
                    + Xs[gr*104+col[1]]*qsm[nl*104+col[1]]
                    + Xs[gr*104+col[2]]*qsm[nl*104+col[2]];
            if (lane < 4){
                v += o3*w2s[col[3]];
                g += Xs[gr*104+col[3]]*qsm[nl*104+col[3]];
            }
            #pragma unroll
            for (int off = 16; off; off >>= 1){
                v += __shfl_down_sync(0xffffffffu, v, off);
                g += __shfl_down_sync(0xffffffffu, g, off);
            }
            if (lane == 0){ ktm[gr] = v; gvm[gr] = g; }
        }
    }
    __syncthreads();

    if (tid < 8){
        int n = n0 + tid;
        int b = n / TM, t = n - b*TM;
        int cnt = min(t, KK);
        float m = -3.4e38f;
        for (int s = 0; s <= cnt; s++){ float v = ktm[tid*11 + s]; if (v > m) m = v; }
        float Z = 0.f, P = 0.f;
        for (int s = 0; s <= cnt; s++){
            float e = __expf(ktm[tid*11 + s] - m);
            Z += e; P += e*gvm[tid*11 + s];
        }
        out[b*TT + 1 + t] = fsig(__fdividef(P, Z));
    }
}

__global__ void tail_k(const float* __restrict__ L, float* __restrict__ out) {
    int i = blockIdx.x*blockDim.x + threadIdx.x;
    if (i < BB) out[i*TT] = 0.5f;
    if (i < BB*DD) {
        int b = i / DD;
        out[BB*TT + i] = L[((size_t)b*TM + (TM-1))*DD + (i - b*DD)];
    }
}

// ---------------- launch ----------------

extern "C" void kernel_launch(void* const* d_in, const int* in_sizes, int n_in,
                              void* d_out, int out_size) {
    const int*   question = (const int*)d_in[0];
    const int*   response = (const int*)d_in[1];
    const int*   maskp    = (const int*)d_in[2];
    const int*   q_nb     = (const int*)d_in[3];
    const int*   s_nb     = (const int*)d_in[4];
    const int*   skidx    = (const int*)d_in[5];
    const int*   skmask   = (const int*)d_in[6];
    const float* emb_q    = (const float*)d_in[7];
    const float* emb_s    = (const float*)d_in[8];
    const float* emb_r    = (const float*)d_in[9];
    const float* Wih      = (const float*)d_in[10];
    const float* lb       = (const float*)d_in[11];
    const float* aggW     = (const float*)d_in[12];
    const float* aggb     = (const float*)d_in[13];
    const float* aggLW    = (const float*)d_in[14];
    const float* aggLb    = (const float*)d_in[15];
    const float* Wq       = (const float*)d_in[16];
    const float* bq       = (const float*)d_in[17];
    const float* w_att    = (const float*)d_in[20];
    float* out = (float*)d_out;

    float* buf = nullptr; int* topk = nullptr;
    cudaGetSymbolAddress((void**)&buf,  g_buf);
    cudaGetSymbolAddress((void**)&topk, g_topk);

    float* pE2  = buf + OFF_E2;
    float* pE1  = buf + OFF_E1;
    float* pE0a = buf + OFF_E0A;
    float* pE1b = buf + OFF_E1B;
    float* pE0b = buf + OFF_E0B;
    float* pAGG = buf + OFF_AGG;
    float* pL   = buf + OFF_L;
    float* pG   = buf + OFF_G;

    const int AFF_SMEM = (10200 + 48*104 + 100)*4;
    const int D_SMEM   = (10200 + 24*104 + 100)*4;
    const int KTF_SMEM = (10200 + 96*104 + 100 + 100 + 8*104 + 96 + 96)*4;
    const int GAT_SMEM = (20200 + 32*204 + 100)*4;
    const int SCO_SMEM = (199*101 + 8*104 + 8*200)*4 + 200*4;
    cudaFuncSetAttribute(stageB_k,      cudaFuncAttributeMaxDynamicSharedMemorySize, AFF_SMEM);
    cudaFuncSetAttribute(stageC_k,      cudaFuncAttributeMaxDynamicSharedMemorySize, AFF_SMEM);
    cudaFuncSetAttribute(stageD_k,      cudaFuncAttributeMaxDynamicSharedMemorySize, D_SMEM);
    cudaFuncSetAttribute(gatesG_k,      cudaFuncAttributeMaxDynamicSharedMemorySize, GAT_SMEM);
    cudaFuncSetAttribute(scores_topk_k, cudaFuncAttributeMaxDynamicSharedMemorySize, SCO_SMEM);
    cudaFuncSetAttribute(ktfinal_k,     cudaFuncAttributeMaxDynamicSharedMemorySize, KTF_SMEM);

    scores_topk_k<<<dim3(BB, 25), 256, SCO_SMEM>>>(question, emb_q, topk);

    stageB_k<<<NB0+NB1+NB2, 256, AFF_SMEM>>>(question, q_nb, s_nb, emb_q, emb_s,
                                             aggW, aggb, pE2, pE1, pE0a);
    stageC_k<<<NB1+NB2, 256, AFF_SMEM>>>(pE1, pE2, pE0a, aggW, aggb, pE1b, pE0b);
    stageD_k<<<NBD, 256, D_SMEM>>>(pE0b, pE1b, aggW, aggb, aggLW, aggLb, pAGG);

    gatesG_k<<<dim3(NN/32, 3), 256, GAT_SMEM>>>(question, response, maskp, emb_q, emb_r,
                                                pAGG, Wih, lb, pG);
    lstm_pw_k<<<(NN*DD + 255)/256, 256>>>(pG, pL);

    ktfinal_k<<<NN/8, 256, KTF_SMEM>>>(question, skidx, skmask, emb_q, emb_s,
                                       pL, topk, Wq, bq, w_att, out);
    tail_k<<<(BB*DD + 255)/256, 256>>>(pL, out);
}

// round 12
// speedup vs baseline: 1.2308x; 1.0533x over previous
#include <cuda_runtime.h>
#include <math.h>

#define BB 32
#define TT 200
#define TM 199
#define NN (BB*TM)        // 6368
#define DD 100
#define KK 10
#define R2 (NN*16)        // 101888
#define R1 (NN*4)         // 25472

#define NB0 2123          // ceil(R2/48)
#define NB1 531           // ceil(R1/48)
#define NB2 133           // ceil(NN/48)
#define NBD 266           // ceil(NN/24)
#define NGATE 597         // 199*3 gates blocks in fused kernel
#define NSCOR 800         // 32*25 scores blocks in fused kernel

typedef unsigned long long ull;

// ---------------- scratch ----------------
__device__ float g_buf[20377600];
__device__ int   g_topk[NN*KK];

static constexpr size_t OFF_E2  = 0;          // R2*100
static constexpr size_t OFF_E1  = 10188800;   // R1*100
static constexpr size_t OFF_E0A = 12736000;   // NN*100
static constexpr size_t OFF_E1B = 13372800;   // R1*100
static constexpr size_t OFF_E0B = 15920000;   // NN*100
static constexpr size_t OFF_AGG = 16556800;   // NN*100
static constexpr size_t OFF_L   = 17193600;   // NN*100
static constexpr size_t OFF_G   = 17830400;   // NN*400

// ---------------- helpers ----------------
__device__ __forceinline__ void fma2(ull& a, ull x, ull w){
    asm("fma.rn.f32x2 %0, %1, %2, %0;" : "+l"(a) : "l"(x), "l"(w));
}
__device__ __forceinline__ float unpack_sum(ull a){
    float lo = __int_as_float((int)(unsigned int)a);
    float hi = __int_as_float((int)(unsigned int)(a >> 32));
    return lo + hi;
}
__device__ __forceinline__ float ftanh(float x){
    float e = __expf(2.f*x);
    return 1.f - __fdividef(2.f, e + 1.f);
}
__device__ __forceinline__ float fsig(float x){
    return __fdividef(1.f, 1.f + __expf(-x));
}

// load 100x100 W into smem pitch 102 (51 ull words; conflict-free LDS.64)
__device__ __forceinline__ void loadW100(const float* __restrict__ W, float* Ws, int tid){
    for (int j = tid; j < 2500; j += 256){
        float4 v = ((const float4*)W)[j];
        int b4 = 4*j; int o = b4/100; int d = b4 - o*100;
        float2* ws = (float2*)&Ws[o*102 + d];
        ws[0] = make_float2(v.x, v.y);
        ws[1] = make_float2(v.z, v.w);
    }
}

// Software-pipelined KR-rows-per-thread 100-d FFMA core.
template<int KR>
__device__ __forceinline__ void core100p(const float* Ws, const float* Xs, int wy,
                                         const int* col, ull (*acc)[4]){
    const ull* WsU = (const ull*)Ws;
    const ull* XsU = (const ull*)Xs;
    const int xbase = wy*KR*52;
    ull w[4], x[KR], nw[4], nx[KR];
    #pragma unroll
    for (int c = 0; c < 4; c++) w[c] = WsU[col[c]*51];
    #pragma unroll
    for (int k = 0; k < KR; k++) x[k] = XsU[xbase + k*52];
    #pragma unroll 1
    for (int dw = 0; dw < 50; dw++){
        int dn = dw + 1;
        #pragma unroll
        for (int c = 0; c < 4; c++) nw[c] = WsU[col[c]*51 + dn];
        #pragma unroll
        for (int k = 0; k < KR; k++) nx[k] = XsU[xbase + k*52 + dn];
        #pragma unroll
        for (int k = 0; k < KR; k++)
            #pragma unroll
            for (int c = 0; c < 4; c++)
                fma2(acc[k][c], x[k], w[c]);
        #pragma unroll
        for (int c = 0; c < 4; c++) w[c] = nw[c];
        #pragma unroll
        for (int k = 0; k < KR; k++) x[k] = nx[k];
    }
}

// ---------------- stage B: fused gather + affine, 3 segments in one grid ----------------

__global__ __launch_bounds__(256) void stageB_k(
    const int* __restrict__ question, const int* __restrict__ q_nb,
    const int* __restrict__ s_nb, const float* __restrict__ emb_q,
    const float* __restrict__ emb_s, const float* __restrict__ aggW,
    const float* __restrict__ aggb, float* __restrict__ E2,
    float* __restrict__ E1, float* __restrict__ E0){
    extern __shared__ float sm[];
    float* Ws = sm;            // 10200
    float* Xs = sm + 10200;    // 48*104
    float* bs = Xs + 48*104;   // 100
    int tid = threadIdx.x, wy = tid >> 5, lane = tid & 31;
    int bid = blockIdx.x;

    int seg, r0, R; const float* W; const float* bias; float* Y;
    if (bid < NB0)            { seg=0; r0=bid*48;            R=R2; W=aggW+20000; bias=aggb+200; Y=E2; }
    else if (bid < NB0+NB1)   { seg=1; r0=(bid-NB0)*48;      R=R1; W=aggW+10000; bias=aggb+100; Y=E1; }
    else                      { seg=2; r0=(bid-NB0-NB1)*48;  R=NN; W=aggW;       bias=aggb;     Y=E0; }

    loadW100(W, Ws, tid);
    if (tid < 100) bs[tid] = bias[tid];

    for (int rr = wy; rr < 48; rr += 8){
        if (lane < 25){
            int r = r0 + rr;
            float4 val = make_float4(0.f,0.f,0.f,0.f);
            if (r < R){
                const float* basep; const int* nb; const float* tbl;
                if (seg == 0){
                    int n = r >> 4, k = (r >> 2) & 3, s = r & 3;
                    int b = n / TM, t = n - b*TM;
                    int q  = question[b*TT + t];
                    int sk = q_nb[q*4 + k];
                    int q2 = s_nb[sk*4 + s];
                    basep = emb_q + (size_t)q2*DD; nb = q_nb + q2*4; tbl = emb_s;
                } else if (seg == 1){
                    int n = r >> 2, k = r & 3;
                    int b = n / TM, t = n - b*TM;
                    int q  = question[b*TT + t];
                    int sk = q_nb[q*4 + k];
                    basep = emb_s + (size_t)sk*DD; nb = s_nb + sk*4; tbl = emb_q;
                } else {
                    int b = r / TM, t = r - b*TM;
                    int q = question[b*TT + t];
                    basep = emb_q + (size_t)q*DD; nb = q_nb + q*4; tbl = emb_s;
                }
                int i0 = nb[0], i1 = nb[1], i2 = nb[2], i3 = nb[3];
                float4 bb = ((const float4*)basep)[lane];
                float4 a = ((const float4*)(tbl + (size_t)i0*DD))[lane];
                float4 c = ((const float4*)(tbl + (size_t)i1*DD))[lane];
                float4 d = ((const float4*)(tbl + (size_t)i2*DD))[lane];
                float4 e = ((const float4*)(tbl + (size_t)i3*DD))[lane];
                val.x = bb.x + 0.25f*(a.x+c.x+d.x+e.x);
                val.y = bb.y + 0.25f*(a.y+c.y+d.y+e.y);
                val.z = bb.z + 0.25f*(a.z+c.z+d.z+e.z);
                val.w = bb.w + 0.25f*(a.w+c.w+d.w+e.w);
            }
            *(float4*)&Xs[rr*104 + 4*lane] = val;
        }
    }
    __syncthreads();

    int c3 = (lane < 4) ? 96 + lane : 96;
    int col[4] = {lane, lane+32, lane+64, c3};
    ull acc[6][4];
    #pragma unroll
    for (int k = 0; k < 6; k++)
        #pragma unroll
        for (int c = 0; c < 4; c++) acc[k][c] = 0ull;
    core100p<6>(Ws, Xs, wy, col, acc);

    #pragma unroll
    for (int k = 0; k < 6; k++){
        int r = r0 + wy*6 + k;
        if (r >= R) continue;
        float* yo = Y + (size_t)r*100;
        yo[col[0]] = ftanh(unpack_sum(acc[k][0]) + bs[col[0]]);
        yo[col[1]] = ftanh(unpack_sum(acc[k][1]) + bs[col[1]]);
        yo[col[2]] = ftanh(unpack_sum(acc[k][2]) + bs[col[2]]);
        if (lane < 4) yo[col[3]] = ftanh(unpack_sum(acc[k][3]) + bs[col[3]]);
    }
}

// ---------------- stage C: X = base + 0.25*sum(kids), two segments ----------------

__global__ __launch_bounds__(256) void stageC_k(
    const float* __restrict__ E1, const float* __restrict__ E2,
    const float* __restrict__ E0a,
    const float* __restrict__ aggW, const float* __restrict__ aggb,
    float* __restrict__ E1b, float* __restrict__ E0b){
    extern __shared__ float sm[];
    float* Ws = sm;
    float* Xs = sm + 10200;
    float* bs = Xs + 48*104;
    int tid = threadIdx.x, wy = tid >> 5, lane = tid & 31;
    int bid = blockIdx.x;

    int r0, R; const float* basep; const float* kids; const float* W; const float* bias; float* Y;
    if (bid < NB1){ r0=bid*48; R=R1; basep=E1; kids=E2; W=aggW+10000; bias=aggb+100; Y=E1b; }
    else          { r0=(bid-NB1)*48; R=NN; basep=E0a; kids=E1; W=aggW; bias=aggb; Y=E0b; }

    loadW100(W, Ws, tid);
    if (tid < 100) bs[tid] = bias[tid];

    for (int rr = wy; rr < 48; rr += 8){
        if (lane < 25){
            int r = r0 + rr;
            float4 val = make_float4(0.f,0.f,0.f,0.f);
            if (r < R){
                const float4* bp = (const float4*)(basep + (size_t)r*100);
                const float4* kp = (const float4*)(kids + (size_t)r*400);
                float4 a = kp[lane], b = kp[25+lane], c = kp[50+lane], d4 = kp[75+lane];
                float4 bb = bp[lane];
                val.x = bb.x + 0.25f*(a.x+b.x+c.x+d4.x);
                val.y = bb.y + 0.25f*(a.y+b.y+c.y+d4.y);
                val.z = bb.z + 0.25f*(a.z+b.z+c.z+d4.z);
                val.w = bb.w + 0.25f*(a.w+b.w+c.w+d4.w);
            }
            *(float4*)&Xs[rr*104 + 4*lane] = val;
        }
    }
    __syncthreads();

    int c3 = (lane < 4) ? 96 + lane : 96;
    int col[4] = {lane, lane+32, lane+64, c3};
    ull acc[6][4];
    #pragma unroll
    for (int k = 0; k < 6; k++)
        #pragma unroll
        for (int c = 0; c < 4; c++) acc[k][c] = 0ull;
    core100p<6>(Ws, Xs, wy, col, acc);

    #pragma unroll
    for (int k = 0; k < 6; k++){
        int r = r0 + wy*6 + k;
        if (r >= R) continue;
        float* yo = Y + (size_t)r*100;
        yo[col[0]] = ftanh(unpack_sum(acc[k][0]) + bs[col[0]]);
        yo[col[1]] = ftanh(unpack_sum(acc[k][1]) + bs[col[1]]);
        yo[col[2]] = ftanh(unpack_sum(acc[k][2]) + bs[col[2]]);
        if (lane < 4) yo[col[3]] = ftanh(unpack_sum(acc[k][3]) + bs[col[3]]);
    }
}

// ---------------- stage D: chained double affine, 24-row tiles (grid 266) ----------------

__global__ __launch_bounds__(256) void stageD_k(
    const float* __restrict__ E0b, const float* __restrict__ E1b,
    const float* __restrict__ aggW, const float* __restrict__ aggb,
    const float* __restrict__ aggLW, const float* __restrict__ aggLb,
    float* __restrict__ AGG){
    extern __shared__ float sm[];
    float* Ws = sm;            // 10200
    float* Xs = sm + 10200;    // 24*104
    float* bs = Xs + 24*104;   // 100
    int tid = threadIdx.x, wy = tid >> 5, lane = tid & 31;
    int r0 = blockIdx.x * 24;

    loadW100(aggW, Ws, tid);
    if (tid < 100) bs[tid] = aggb[tid];

    for (int rr = wy; rr < 24; rr += 8){
        if (lane < 25){
            int r = r0 + rr;
            float4 val = make_float4(0.f,0.f,0.f,0.f);
            if (r < NN){
                const float4* bp = (const float4*)(E0b + (size_t)r*100);
                const float4* kp = (const float4*)(E1b + (size_t)r*400);
                float4 a = kp[lane], b = kp[25+lane], c = kp[50+lane], d4 = kp[75+lane];
                float4 bb = bp[lane];
                val.x = bb.x + 0.25f*(a.x+b.x+c.x+d4.x);
                val.y = bb.y + 0.25f*(a.y+b.y+c.y+d4.y);
                val.z = bb.z + 0.25f*(a.z+b.z+c.z+d4.z);
                val.w = bb.w + 0.25f*(a.w+b.w+c.w+d4.w);
            }
            *(float4*)&Xs[rr*104 + 4*lane] = val;
        }
    }
    __syncthreads();

    int c3 = (lane < 4) ? 96 + lane : 96;
    int col[4] = {lane, lane+32, lane+64, c3};
    ull acc[3][4];
    #pragma unroll
    for (int k = 0; k < 3; k++)
        #pragma unroll
        for (int c = 0; c < 4; c++) acc[k][c] = 0ull;
    core100p<3>(Ws, Xs, wy, col, acc);

    #pragma unroll
    for (int k = 0; k < 3; k++){
        int rr = wy*3 + k;
        int r = r0 + rr;
        if (r >= NN) continue;
        Xs[rr*104 + col[0]] = ftanh(unpack_sum(acc[k][0]) + bs[col[0]]);
        Xs[rr*104 + col[1]] = ftanh(unpack_sum(acc[k][1]) + bs[col[1]]);
        Xs[rr*104 + col[2]] = ftanh(unpack_sum(acc[k][2]) + bs[col[2]]);
        if (lane < 4) Xs[rr*104 + col[3]] = ftanh(unpack_sum(acc[k][3]) + bs[col[3]]);
    }
    __syncthreads();

    loadW100(aggLW, Ws, tid);
    if (tid < 100) bs[tid] = aggLb[tid];
    __syncthreads();

    #pragma unroll
    for (int k = 0; k < 3; k++)
        #pragma unroll
        for (int c = 0; c < 4; c++) acc[k][c] = 0ull;
    core100p<3>(Ws, Xs, wy, col, acc);

    #pragma unroll
    for (int k = 0; k < 3; k++){
        int r = r0 + wy*3 + k;
        if (r >= NN) continue;
        float* yo = AGG + (size_t)r*100;
        yo[col[0]] = ftanh(unpack_sum(acc[k][0]) + bs[col[0]]);
        yo[col[1]] = ftanh(unpack_sum(acc[k][1]) + bs[col[1]]);
        yo[col[2]] = ftanh(unpack_sum(acc[k][2]) + bs[col[2]]);
        if (lane < 4) yo[col[3]] = ftanh(unpack_sum(acc[k][3]) + bs[col[3]]);
    }
}

// ---------------- FUSED: LSTM gates (blocks 0..596) + scores/top-10 (blocks 597..1396) ----------------
// Gates: pitch-202 pipelined 200-d core, gate chunk gy in {0,1,2} -> offsets {0,200,300}.
// Scores: per-(b, t-octet) warp dot products + iterative top-10. Independent workloads;
// both ran at 2 blocks/SM standalone (91KB/107KB smem), so fusion keeps per-branch occupancy.

__global__ __launch_bounds__(256) void gatesScores_k(
    const int* __restrict__ question, const int* __restrict__ response,
    const int* __restrict__ maskp, const float* __restrict__ emb_q,
    const float* __restrict__ emb_r, const float* __restrict__ AGG,
    const float* __restrict__ Wih, const float* __restrict__ lb,
    float* __restrict__ G, int* __restrict__ topk){
    extern __shared__ float sm[];
    int tid = threadIdx.x, wy = tid >> 5, lane = tid & 31;
    int bid = blockIdx.x;

    if (bid < NGATE){
        // ---- gates branch ----
        float* Ws = sm;             // 100 x 202
        float* Xs = sm + 20200;     // 32 x 204
        float* bs = Xs + 32*204;    // 100
        int gy = bid / 199;
        int bx = bid - gy*199;
        int ob = (gy == 0) ? 0 : (gy + 1)*100;   // 0, 200, 300
        const float* W = Wih + (size_t)ob*200;

        for (int j = tid; j < 5000; j += 256){
            float4 v = ((const float4*)W)[j];
            int b4 = 4*j; int o = b4/200; int d = b4 - o*200;
            float2* ws = (float2*)&Ws[o*202 + d];
            ws[0] = make_float2(v.x, v.y);
            ws[1] = make_float2(v.z, v.w);
        }
        if (tid < 100) bs[tid] = lb[ob + tid];

        int r0 = bx * 32;
        for (int rr = wy; rr < 32; rr += 8){
            if (lane < 25){
                int r = r0 + rr;
                int b = r / TM, t = r - b*TM;
                int q   = question[b*TT + t];
                int m   = maskp[b*TT + t];
                int rsp = response[b*TT + t];
                const float4* s1 = (const float4*)((m == 1) ? (AGG + (size_t)r*100)
                                                            : (emb_q + (size_t)q*100));
                const float4* s2 = (const float4*)(emb_r + (size_t)rsp*100);
                *(float4*)&Xs[rr*204 + 4*lane]       = s1[lane];
                *(float4*)&Xs[rr*204 + 100 + 4*lane] = s2[lane];
            }
        }
        __syncthreads();

        int c3 = (lane < 4) ? 96 + lane : 96;
        int col[4] = {lane, lane+32, lane+64, c3};
        ull acc[4][4];
        #pragma unroll
        for (int k = 0; k < 4; k++)
            #pragma unroll
            for (int c = 0; c < 4; c++) acc[k][c] = 0ull;

        {
            const ull* WsU = (const ull*)Ws;
            const ull* XsU = (const ull*)Xs;
            const int xbase = wy*4*102;
            ull w[4], x[4], nw[4], nx[4];
            #pragma unroll
            for (int c = 0; c < 4; c++) w[c] = WsU[col[c]*101];
            #pragma unroll
            for (int k = 0; k < 4; k++) x[k] = XsU[xbase + k*102];
            #pragma unroll 1
            for (int dw = 0; dw < 100; dw++){
                int dn = dw + 1;
                #pragma unroll
                for (int c = 0; c < 4; c++) nw[c] = WsU[col[c]*101 + dn];
                #pragma unroll
                for (int k = 0; k < 4; k++) nx[k] = XsU[xbase + k*102 + dn];
                #pragma unroll
                for (int k = 0; k < 4; k++)
                    #pragma unroll
                    for (int c = 0; c < 4; c++)
                        fma2(acc[k][c], x[k], w[c]);
                #pragma unroll
                for (int c = 0; c < 4; c++) w[c] = nw[c];
                #pragma unroll
                for (int k = 0; k < 4; k++) x[k] = nx[k];
            }
        }

        #pragma unroll
        for (int k = 0; k < 4; k++){
            int r = r0 + wy*4 + k;
            if (r >= NN) continue;
            float* go = G + (size_t)r*400 + ob;
            go[col[0]] = unpack_sum(acc[k][0]) + bs[col[0]];
            go[col[1]] = unpack_sum(acc[k][1]) + bs[col[1]];
            go[col[2]] = unpack_sum(acc[k][2]) + bs[col[2]];
            if (lane < 4) go[col[3]] = unpack_sum(acc[k][3]) + bs[col[3]];
        }
    } else {
        // ---- scores + top-10 branch ----
        float* P    = sm;              // [199][101]
        float* qrow = P + 199*101;     // [8][104]
        float* srow = qrow + 8*104;    // [8][200]
        int*   qidx = (int*)(srow + 8*200);  // [200]
        int sid = bid - NGATE;
        int b  = sid & 31;             // sid % 32
        int ty = sid >> 5;             // sid / 32, 0..24
        if (tid < TT) qidx[tid] = question[b*TT + tid];
        __syncthreads();
        int tmax = min(TM - 1, ty*8 + 7);
        int rmax = tmax;
        for (int i = tid; i < rmax*DD; i += 256) {
            int s = i / DD, d = i - s*DD;
            P[s*101 + d] = emb_q[(size_t)qidx[s]*DD + d];
        }
        __syncthreads();
        int t = ty*8 + wy;
        if (t >= TM) return;
        int qv = qidx[t + 1];
        for (int d = lane; d < DD; d += 32) qrow[wy*104 + d] = emb_q[(size_t)qv*DD + d];
        __syncwarp();
        for (int s = lane; s < t; s += 32) {
            float acc = 0.f;
            const float* pr = P + s*101;
            const float* qr = qrow + wy*104;
            #pragma unroll 4
            for (int d = 0; d < DD; d++) acc += qr[d]*pr[d];
            srow[wy*200 + s] = acc;
        }
        __syncwarp();
        int n = b*TM + t;
        int cnt = min(t, KK);
        for (int sel = 0; sel < KK; sel++) {
            if (sel < cnt) {
                float bv = -3.4e38f; unsigned bi = 0xffffffffu;
                for (int s = lane; s < t; s += 32) {
                    float v = srow[wy*200 + s];
                    if (v > bv) { bv = v; bi = (unsigned)s; }
                }
                #pragma unroll
                for (int off = 16; off; off >>= 1) {
                    float    ov = __shfl_down_sync(0xffffffffu, bv, off);
                    unsigned oi = __shfl_down_sync(0xffffffffu, bi, off);
                    if (ov > bv || (ov == bv && oi < bi)) { bv = ov; bi = oi; }
                }
                bi = __shfl_sync(0xffffffffu, bi, 0);
                if (lane == 0) { topk[n*KK + sel] = (int)bi; srow[wy*200 + bi] = -3.4e38f; }
                __syncwarp();
            } else if (lane == 0) {
                topk[n*KK + sel] = -1;
            }
        }
    }
}

// ---------------- LSTM pointwise + output tail (fused) ----------------
__global__ void lstm_pw_k(const float* __restrict__ G, float* __restrict__ L,
                          float* __restrict__ out) {
    int i = blockIdx.x*blockDim.x + threadIdx.x;
    if (i < BB) out[i*TT] = 0.5f;
    if (i >= NN*DD) return;
    int n = i/DD, d = i - n*DD;
    const float* g = G + (size_t)n*400;
    float gi = g[d], gg = g[200+d], go = g[300+d];
    float val = fsig(go) * ftanh(fsig(gi) * ftanh(gg));
    L[i] = val;
    int b = n / TM, t = n - b*TM;
    if (t == TM-1) out[BB*TT + b*DD + d] = val;
}

// ---------------- fused KT affine + attention + output: 4 n's (44 hist rows) / block ----------------

__global__ __launch_bounds__(256) void ktfinal_k(
    const int* __restrict__ question, const int* __restrict__ skidx,
    const int* __restrict__ skmask, const float* __restrict__ emb_q,
    const float* __restrict__ emb_s, const float* __restrict__ L,
    const int* __restrict__ topk, const float* __restrict__ Wq,
    const float* __restrict__ bq, const float* __restrict__ w_att,
    float* __restrict__ out){
    extern __shared__ float sm[];
    float* Ws  = sm;               // 10200
    float* Xs  = sm + 10200;       // 48*104
    float* bs  = Xs + 48*104;      // 100
    float* w2s = bs + 100;         // 100
    float* qsm = w2s + 100;        // 4*104
    float* ktm = qsm + 4*104;      // 48
    float* gvm = ktm + 48;         // 48
    int tid = threadIdx.x, wy = tid >> 5, lane = tid & 31;
    int n0 = blockIdx.x * 4;

    loadW100(Wq, Ws, tid);
    if (tid < 100) { bs[tid] = bq[tid]; w2s[tid] = w_att[100 + tid]; }

    for (int rr = wy; rr < 48; rr += 8){
        if (lane < 25){
            float4 val = make_float4(0.f,0.f,0.f,0.f);
            if (rr < 44){
                int n = n0 + rr/11, s = rr - (rr/11)*11;
                int b = n / TM, t = n - b*TM;
                int cnt = min(t, KK);
                const float* src = nullptr;
                if (s == 0) src = L + (size_t)n*100;
                else if (s-1 < cnt){
                    int idx = topk[n*KK + s - 1];
                    if (idx > 0) src = L + ((size_t)b*TM + idx)*100;
                }
                if (src) val = ((const float4*)src)[lane];
            }
            *(float4*)&Xs[rr*104 + 4*lane] = val;
        }
    }
    if (wy < 4){
        int n = n0 + wy;
        int b = n / TM, t = n - b*TM;
        int qv = question[b*TT + t + 1];
        if (lane < 25){
            float4 v = ((const float4*)(emb_q + (size_t)qv*100))[lane];
            #pragma unroll
            for (int i = 0; i < 4; i++){
                if (skmask[qv*4 + i] != 0){
                    float4 e = ((const float4*)(emb_s + (size_t)skidx[qv*4 + i]*100))[lane];
                    v.x += e.x; v.y += e.y; v.z += e.z; v.w += e.w;
                }
            }
            *(float4*)&qsm[wy*104 + 4*lane] = v;
        }
    }
    __syncthreads();

    int c3 = (lane < 4) ? 96 + lane : 96;
    int col[4] = {lane, lane+32, lane+64, c3};
    ull acc[6][4];
    #pragma unroll
    for (int k = 0; k < 6; k++)
        #pragma unroll
        for (int c = 0; c < 4; c++) acc[k][c] = 0ull;
    core100p<6>(Ws, Xs, wy, col, acc);

    #pragma unroll
    for (int k = 0; k < 6; k++){
        int rr = wy*6 + k;
        if (rr >= 44) continue;
        int nl = rr / 11;
        float o0 = ftanh(unpack_sum(acc[k][0]) + bs[col[0]]);
        float o1 = ftanh(unpack_sum(acc[k][1]) + bs[col[1]]);
        float o2 = ftanh(unpack_sum(acc[k][2]) + bs[col[2]]);
        float o3 = ftanh(unpack_sum(acc[k][3]) + bs[col[3]]);
        float v = o0*w2s[col[0]] + o1*w2s[col[1]] + o2*w2s[col[2]];
        float g = Xs[rr*104+col[0]]*qsm[nl*104+col[0]]
                + Xs[rr*104+col[1]]*qsm[nl*104+col[1]]
                + Xs[rr*104+col[2]]*qsm[nl*104+col[2]];
        if (lane < 4){
            v += o3*w2s[col[3]];
            g += Xs[rr*104+col[3]]*qsm[nl*104+col[3]];
        }
        #pragma unroll
        for (int off = 16; off; off >>= 1){
            v += __shfl_down_sync(0xffffffffu, v, off);
            g += __shfl_down_sync(0xffffffffu, g, off);
        }
        if (lane == 0){ ktm[rr] = v; gvm[rr] = g; }
    }
    __syncthreads();

    if (tid < 4){
        int n = n0 + tid;
        int b = n / TM, t = n - b*TM;
        int cnt = min(t, KK);
        float m = -3.4e38f;
        for (int s = 0; s <= cnt; s++){ float v = ktm[tid*11 + s]; if (v > m) m = v; }
        float Z = 0.f, P = 0.f;
        for (int s = 0; s <= cnt; s++){
            float e = __expf(ktm[tid*11 + s] - m);
            Z += e; P += e*gvm[tid*11 + s];
        }
        out[b*TT + 1 + t] = fsig(__fdividef(P, Z));
    }
}

// ---------------- launch ----------------

extern "C" void kernel_launch(void* const* d_in, const int* in_sizes, int n_in,
                              void* d_out, int out_size) {
    const int*   question = (const int*)d_in[0];
    const int*   response = (const int*)d_in[1];
    const int*   maskp    = (const int*)d_in[2];
    const int*   q_nb     = (const int*)d_in[3];
    const int*   s_nb     = (const int*)d_in[4];
    const int*   skidx    = (const int*)d_in[5];
    const int*   skmask   = (const int*)d_in[6];
    const float* emb_q    = (const float*)d_in[7];
    const float* emb_s    = (const float*)d_in[8];
    const float* emb_r    = (const float*)d_in[9];
    const float* Wih      = (const float*)d_in[10];
    const float* lb       = (const float*)d_in[11];
    const float* aggW     = (const float*)d_in[12];
    const float* aggb     = (const float*)d_in[13];
    const float* aggLW    = (const float*)d_in[14];
    const float* aggLb    = (const float*)d_in[15];
    const float* Wq       = (const float*)d_in[16];
    const float* bq       = (const float*)d_in[17];
    const float* w_att    = (const float*)d_in[20];
    float* out = (float*)d_out;

    float* buf = nullptr; int* topk = nullptr;
    cudaGetSymbolAddress((void**)&buf,  g_buf);
    cudaGetSymbolAddress((void**)&topk, g_topk);

    float* pE2  = buf + OFF_E2;
    float* pE1  = buf + OFF_E1;
    float* pE0a = buf + OFF_E0A;
    float* pE1b = buf + OFF_E1B;
    float* pE0b = buf + OFF_E0B;
    float* pAGG = buf + OFF_AGG;
    float* pL   = buf + OFF_L;
    float* pG   = buf + OFF_G;

    const int AFF_SMEM = (10200 + 48*104 + 100)*4;
    const int D_SMEM   = (10200 + 24*104 + 100)*4;
    const int KTF_SMEM = (10200 + 48*104 + 100 + 100 + 4*104 + 48 + 48)*4;
    const int GAT_SMEM = (20200 + 32*204 + 100)*4;                       // 107312
    const int SCO_SMEM = (199*101 + 8*104 + 8*200)*4 + 200*4;            // 90924
    const int GSC_SMEM = (GAT_SMEM > SCO_SMEM) ? GAT_SMEM : SCO_SMEM;
    cudaFuncSetAttribute(stageB_k,      cudaFuncAttributeMaxDynamicSharedMemorySize, AFF_SMEM);
    cudaFuncSetAttribute(stageC_k,      cudaFuncAttributeMaxDynamicSharedMemorySize, AFF_SMEM);
    cudaFuncSetAttribute(stageD_k,      cudaFuncAttributeMaxDynamicSharedMemorySize, D_SMEM);
    cudaFuncSetAttribute(gatesScores_k, cudaFuncAttributeMaxDynamicSharedMemorySize, GSC_SMEM);
    cudaFuncSetAttribute(ktfinal_k,     cudaFuncAttributeMaxDynamicSharedMemorySize, KTF_SMEM);

    stageB_k<<<NB0+NB1+NB2, 256, AFF_SMEM>>>(question, q_nb, s_nb, emb_q, emb_s,
                                             aggW, aggb, pE2, pE1, pE0a);
    stageC_k<<<NB1+NB2, 256, AFF_SMEM>>>(pE1, pE2, pE0a, aggW, aggb, pE1b, pE0b);
    stageD_k<<<NBD, 256, D_SMEM>>>(pE0b, pE1b, aggW, aggb, aggLW, aggLb, pAGG);

    gatesScores_k<<<NGATE+NSCOR, 256, GSC_SMEM>>>(question, response, maskp, emb_q, emb_r,
                                                  pAGG, Wih, lb, pG, topk);
    lstm_pw_k<<<(NN*DD + 255)/256, 256>>>(pG, pL, out);

    ktfinal_k<<<NN/4, 256, KTF_SMEM>>>(question, skidx, skmask, emb_q, emb_s,
                                       pL, topk, Wq, bq, w_att, out);
}

// round 13
// speedup vs baseline: 1.3080x; 1.0628x over previous
#include <cuda_runtime.h>
#include <math.h>

#define BB 32
#define TT 200
#define TM 199
#define NN (BB*TM)        // 6368
#define DD 100
#define KK 10
#define R2 (NN*16)        // 101888
#define R1 (NN*4)         // 25472

#define NB0 2123          // ceil(R2/48)
#define NB1 531           // ceil(R1/48)
#define NB2 133           // ceil(NN/48)
#define NBD 266           // ceil(NN/24)
#define NGATE 597         // 199*3 gates blocks in fused kernel
#define NSCOR 800         // 32*25 scores blocks in fused kernel

typedef unsigned long long ull;

// ---------------- scratch ----------------
__device__ float g_buf[20377600];
__device__ int   g_topk[NN*KK];

static constexpr size_t OFF_E2  = 0;          // R2*100
static constexpr size_t OFF_E1  = 10188800;   // R1*100
static constexpr size_t OFF_E0A = 12736000;   // NN*100
static constexpr size_t OFF_E1B = 13372800;   // R1*100
static constexpr size_t OFF_E0B = 15920000;   // NN*100
static constexpr size_t OFF_AGG = 16556800;   // NN*100
static constexpr size_t OFF_L   = 17193600;   // NN*100
static constexpr size_t OFF_G   = 17830400;   // NN*400

// ---------------- helpers ----------------
__device__ __forceinline__ void fma2(ull& a, ull x, ull w){
    asm("fma.rn.f32x2 %0, %1, %2, %0;" : "+l"(a) : "l"(x), "l"(w));
}
__device__ __forceinline__ float unpack_sum(ull a){
    float lo = __int_as_float((int)(unsigned int)a);
    float hi = __int_as_float((int)(unsigned int)(a >> 32));
    return lo + hi;
}
__device__ __forceinline__ float ftanh(float x){
    float e = __expf(2.f*x);
    return 1.f - __fdividef(2.f, e + 1.f);
}
__device__ __forceinline__ float fsig(float x){
    return __fdividef(1.f, 1.f + __expf(-x));
}

// load 100x100 W into smem pitch 102 (51 ull words; conflict-free LDS.64)
__device__ __forceinline__ void loadW100(const float* __restrict__ W, float* Ws, int tid){
    for (int j = tid; j < 2500; j += 256){
        float4 v = ((const float4*)W)[j];
        int b4 = 4*j; int o = b4/100; int d = b4 - o*100;
        float2* ws = (float2*)&Ws[o*102 + d];
        ws[0] = make_float2(v.x, v.y);
        ws[1] = make_float2(v.z, v.w);
    }
}

// Software-pipelined KR-rows-per-thread 100-d FFMA core.
template<int KR>
__device__ __forceinline__ void core100p(const float* Ws, const float* Xs, int wy,
                                         const int* col, ull (*acc)[4]){
    const ull* WsU = (const ull*)Ws;
    const ull* XsU = (const ull*)Xs;
    const int xbase = wy*KR*52;
    ull w[4], x[KR], nw[4], nx[KR];
    #pragma unroll
    for (int c = 0; c < 4; c++) w[c] = WsU[col[c]*51];
    #pragma unroll
    for (int k = 0; k < KR; k++) x[k] = XsU[xbase + k*52];
    #pragma unroll 1
    for (int dw = 0; dw < 50; dw++){
        int dn = dw + 1;
        #pragma unroll
        for (int c = 0; c < 4; c++) nw[c] = WsU[col[c]*51 + dn];
        #pragma unroll
        for (int k = 0; k < KR; k++) nx[k] = XsU[xbase + k*52 + dn];
        #pragma unroll
        for (int k = 0; k < KR; k++)
            #pragma unroll
            for (int c = 0; c < 4; c++)
                fma2(acc[k][c], x[k], w[c]);
        #pragma unroll
        for (int c = 0; c < 4; c++) w[c] = nw[c];
        #pragma unroll
        for (int k = 0; k < KR; k++) x[k] = nx[k];
    }
}

// ---------------- stage B: fused gather + affine, 3 segments in one grid ----------------

__global__ __launch_bounds__(256) void stageB_k(
    const int* __restrict__ question, const int* __restrict__ q_nb,
    const int* __restrict__ s_nb, const float* __restrict__ emb_q,
    const float* __restrict__ emb_s, const float* __restrict__ aggW,
    const float* __restrict__ aggb, float* __restrict__ E2,
    float* __restrict__ E1, float* __restrict__ E0){
    extern __shared__ float sm[];
    float* Ws = sm;            // 10200
    float* Xs = sm + 10200;    // 48*104
    float* bs = Xs + 48*104;   // 100
    int tid = threadIdx.x, wy = tid >> 5, lane = tid & 31;
    int bid = blockIdx.x;

    int seg, r0, R; const float* W; const float* bias; float* Y;
    if (bid < NB0)            { seg=0; r0=bid*48;            R=R2; W=aggW+20000; bias=aggb+200; Y=E2; }
    else if (bid < NB0+NB1)   { seg=1; r0=(bid-NB0)*48;      R=R1; W=aggW+10000; bias=aggb+100; Y=E1; }
    else                      { seg=2; r0=(bid-NB0-NB1)*48;  R=NN; W=aggW;       bias=aggb;     Y=E0; }

    loadW100(W, Ws, tid);
    if (tid < 100) bs[tid] = bias[tid];

    for (int rr = wy; rr < 48; rr += 8){
        if (lane < 25){
            int r = r0 + rr;
            float4 val = make_float4(0.f,0.f,0.f,0.f);
            if (r < R){
                const float* basep; const int* nb; const float* tbl;
                if (seg == 0){
                    int n = r >> 4, k = (r >> 2) & 3, s = r & 3;
                    int b = n / TM, t = n - b*TM;
                    int q  = question[b*TT + t];
                    int sk = q_nb[q*4 + k];
                    int q2 = s_nb[sk*4 + s];
                    basep = emb_q + (size_t)q2*DD; nb = q_nb + q2*4; tbl = emb_s;
                } else if (seg == 1){
                    int n = r >> 2, k = r & 3;
                    int b = n / TM, t = n - b*TM;
                    int q  = question[b*TT + t];
                    int sk = q_nb[q*4 + k];
                    basep = emb_s + (size_t)sk*DD; nb = s_nb + sk*4; tbl = emb_q;
                } else {
                    int b = r / TM, t = r - b*TM;
                    int q = question[b*TT + t];
                    basep = emb_q + (size_t)q*DD; nb = q_nb + q*4; tbl = emb_s;
                }
                int i0 = nb[0], i1 = nb[1], i2 = nb[2], i3 = nb[3];
                float4 bb = ((const float4*)basep)[lane];
                float4 a = ((const float4*)(tbl + (size_t)i0*DD))[lane];
                float4 c = ((const float4*)(tbl + (size_t)i1*DD))[lane];
                float4 d = ((const float4*)(tbl + (size_t)i2*DD))[lane];
                float4 e = ((const float4*)(tbl + (size_t)i3*DD))[lane];
                val.x = bb.x + 0.25f*(a.x+c.x+d.x+e.x);
                val.y = bb.y + 0.25f*(a.y+c.y+d.y+e.y);
                val.z = bb.z + 0.25f*(a.z+c.z+d.z+e.z);
                val.w = bb.w + 0.25f*(a.w+c.w+d.w+e.w);
            }
            *(float4*)&Xs[rr*104 + 4*lane] = val;
        }
    }
    __syncthreads();

    int c3 = (lane < 4) ? 96 + lane : 96;
    int col[4] = {lane, lane+32, lane+64, c3};
    ull acc[6][4];
    #pragma unroll
    for (int k = 0; k < 6; k++)
        #pragma unroll
        for (int c = 0; c < 4; c++) acc[k][c] = 0ull;
    core100p<6>(Ws, Xs, wy, col, acc);

    #pragma unroll
    for (int k = 0; k < 6; k++){
        int r = r0 + wy*6 + k;
        if (r >= R) continue;
        float* yo = Y + (size_t)r*100;
        yo[col[0]] = ftanh(unpack_sum(acc[k][0]) + bs[col[0]]);
        yo[col[1]] = ftanh(unpack_sum(acc[k][1]) + bs[col[1]]);
        yo[col[2]] = ftanh(unpack_sum(acc[k][2]) + bs[col[2]]);
        if (lane < 4) yo[col[3]] = ftanh(unpack_sum(acc[k][3]) + bs[col[3]]);
    }
}

// ---------------- stage C: X = base + 0.25*sum(kids), two segments ----------------

__global__ __launch_bounds__(256) void stageC_k(
    const float* __restrict__ E1, const float* __restrict__ E2,
    const float* __restrict__ E0a,
    const float* __restrict__ aggW, const float* __restrict__ aggb,
    float* __restrict__ E1b, float* __restrict__ E0b){
    extern __shared__ float sm[];
    float* Ws = sm;
    float* Xs = sm + 10200;
    float* bs = Xs + 48*104;
    int tid = threadIdx.x, wy = tid >> 5, lane = tid & 31;
    int bid = blockIdx.x;

    int r0, R; const float* basep; const float* kids; const float* W; const float* bias; float* Y;
    if (bid < NB1){ r0=bid*48; R=R1; basep=E1; kids=E2; W=aggW+10000; bias=aggb+100; Y=E1b; }
    else          { r0=(bid-NB1)*48; R=NN; basep=E0a; kids=E1; W=aggW; bias=aggb; Y=E0b; }

    loadW100(W, Ws, tid);
    if (tid < 100) bs[tid] = bias[tid];

    for (int rr = wy; rr < 48; rr += 8){
        if (lane < 25){
            int r = r0 + rr;
            float4 val = make_float4(0.f,0.f,0.f,0.f);
            if (r < R){
                const float4* bp = (const float4*)(basep + (size_t)r*100);
                const float4* kp = (const float4*)(kids + (size_t)r*400);
                float4 a = kp[lane], b = kp[25+lane], c = kp[50+lane], d4 = kp[75+lane];
                float4 bb = bp[lane];
                val.x = bb.x + 0.25f*(a.x+b.x+c.x+d4.x);
                val.y = bb.y + 0.25f*(a.y+b.y+c.y+d4.y);
                val.z = bb.z + 0.25f*(a.z+b.z+c.z+d4.z);
                val.w = bb.w + 0.25f*(a.w+b.w+c.w+d4.w);
            }
            *(float4*)&Xs[rr*104 + 4*lane] = val;
        }
    }
    __syncthreads();

    int c3 = (lane < 4) ? 96 + lane : 96;
    int col[4] = {lane, lane+32, lane+64, c3};
    ull acc[6][4];
    #pragma unroll
    for (int k = 0; k < 6; k++)
        #pragma unroll
        for (int c = 0; c < 4; c++) acc[k][c] = 0ull;
    core100p<6>(Ws, Xs, wy, col, acc);

    #pragma unroll
    for (int k = 0; k < 6; k++){
        int r = r0 + wy*6 + k;
        if (r >= R) continue;
        float* yo = Y + (size_t)r*100;
        yo[col[0]] = ftanh(unpack_sum(acc[k][0]) + bs[col[0]]);
        yo[col[1]] = ftanh(unpack_sum(acc[k][1]) + bs[col[1]]);
        yo[col[2]] = ftanh(unpack_sum(acc[k][2]) + bs[col[2]]);
        if (lane < 4) yo[col[3]] = ftanh(unpack_sum(acc[k][3]) + bs[col[3]]);
    }
}

// ---------------- stage D: chained double affine, 24-row tiles (grid 266) ----------------

__global__ __launch_bounds__(256) void stageD_k(
    const float* __restrict__ E0b, const float* __restrict__ E1b,
    const float* __restrict__ aggW, const float* __restrict__ aggb,
    const float* __restrict__ aggLW, const float* __restrict__ aggLb,
    float* __restrict__ AGG){
    extern __shared__ float sm[];
    float* Ws = sm;            // 10200
    float* Xs = sm + 10200;    // 24*104
    float* bs = Xs + 24*104;   // 100
    int tid = threadIdx.x, wy = tid >> 5, lane = tid & 31;
    int r0 = blockIdx.x * 24;

    loadW100(aggW, Ws, tid);
    if (tid < 100) bs[tid] = aggb[tid];

    for (int rr = wy; rr < 24; rr += 8){
        if (lane < 25){
            int r = r0 + rr;
            float4 val = make_float4(0.f,0.f,0.f,0.f);
            if (r < NN){
                const float4* bp = (const float4*)(E0b + (size_t)r*100);
                const float4* kp = (const float4*)(E1b + (size_t)r*400);
                float4 a = kp[lane], b = kp[25+lane], c = kp[50+lane], d4 = kp[75+lane];
                float4 bb = bp[lane];
                val.x = bb.x + 0.25f*(a.x+b.x+c.x+d4.x);
                val.y = bb.y + 0.25f*(a.y+b.y+c.y+d4.y);
                val.z = bb.z + 0.25f*(a.z+b.z+c.z+d4.z);
                val.w = bb.w + 0.25f*(a.w+b.w+c.w+d4.w);
            }
            *(float4*)&Xs[rr*104 + 4*lane] = val;
        }
    }
    __syncthreads();

    int c3 = (lane < 4) ? 96 + lane : 96;
    int col[4] = {lane, lane+32, lane+64, c3};
    ull acc[3][4];
    #pragma unroll
    for (int k = 0; k < 3; k++)
        #pragma unroll
        for (int c = 0; c < 4; c++) acc[k][c] = 0ull;
    core100p<3>(Ws, Xs, wy, col, acc);

    #pragma unroll
    for (int k = 0; k < 3; k++){
        int rr = wy*3 + k;
        int r = r0 + rr;
        if (r >= NN) continue;
        Xs[rr*104 + col[0]] = ftanh(unpack_sum(acc[k][0]) + bs[col[0]]);
        Xs[rr*104 + col[1]] = ftanh(unpack_sum(acc[k][1]) + bs[col[1]]);
        Xs[rr*104 + col[2]] = ftanh(unpack_sum(acc[k][2]) + bs[col[2]]);
        if (lane < 4) Xs[rr*104 + col[3]] = ftanh(unpack_sum(acc[k][3]) + bs[col[3]]);
    }
    __syncthreads();

    loadW100(aggLW, Ws, tid);
    if (tid < 100) bs[tid] = aggLb[tid];
    __syncthreads();

    #pragma unroll
    for (int k = 0; k < 3; k++)
        #pragma unroll
        for (int c = 0; c < 4; c++) acc[k][c] = 0ull;
    core100p<3>(Ws, Xs, wy, col, acc);

    #pragma unroll
    for (int k = 0; k < 3; k++){
        int r = r0 + wy*3 + k;
        if (r >= NN) continue;
        float* yo = AGG + (size_t)r*100;
        yo[col[0]] = ftanh(unpack_sum(acc[k][0]) + bs[col[0]]);
        yo[col[1]] = ftanh(unpack_sum(acc[k][1]) + bs[col[1]]);
        yo[col[2]] = ftanh(unpack_sum(acc[k][2]) + bs[col[2]]);
        if (lane < 4) yo[col[3]] = ftanh(unpack_sum(acc[k][3]) + bs[col[3]]);
    }
}

// ---------------- FUSED: LSTM gates (blocks 0..596) + scores/top-10 (blocks 597..1396) ----------------
// Scores branch vectorized: P pitch 102 (51 ull/row, lane-stride conflict-free),
// dot loop = 50 packed fma2 over ull pairs; staging uses float2.

__global__ __launch_bounds__(256) void gatesScores_k(
    const int* __restrict__ question, const int* __restrict__ response,
    const int* __restrict__ maskp, const float* __restrict__ emb_q,
    const float* __restrict__ emb_r, const float* __restrict__ AGG,
    const float* __restrict__ Wih, const float* __restrict__ lb,
    float* __restrict__ G, int* __restrict__ topk){
    extern __shared__ float sm[];
    int tid = threadIdx.x, wy = tid >> 5, lane = tid & 31;
    int bid = blockIdx.x;

    if (bid < NGATE){
        // ---- gates branch ----
        float* Ws = sm;             // 100 x 202
        float* Xs = sm + 20200;     // 32 x 204
        float* bs = Xs + 32*204;    // 100
        int gy = bid / 199;
        int bx = bid - gy*199;
        int ob = (gy == 0) ? 0 : (gy + 1)*100;   // 0, 200, 300
        const float* W = Wih + (size_t)ob*200;

        for (int j = tid; j < 5000; j += 256){
            float4 v = ((const float4*)W)[j];
            int b4 = 4*j; int o = b4/200; int d = b4 - o*200;
            float2* ws = (float2*)&Ws[o*202 + d];
            ws[0] = make_float2(v.x, v.y);
            ws[1] = make_float2(v.z, v.w);
        }
        if (tid < 100) bs[tid] = lb[ob + tid];

        int r0 = bx * 32;
        for (int rr = wy; rr < 32; rr += 8){
            if (lane < 25){
                int r = r0 + rr;
                int b = r / TM, t = r - b*TM;
                int q   = question[b*TT + t];
                int m   = maskp[b*TT + t];
                int rsp = response[b*TT + t];
                const float4* s1 = (const float4*)((m == 1) ? (AGG + (size_t)r*100)
                                                            : (emb_q + (size_t)q*100));
                const float4* s2 = (const float4*)(emb_r + (size_t)rsp*100);
                *(float4*)&Xs[rr*204 + 4*lane]       = s1[lane];
                *(float4*)&Xs[rr*204 + 100 + 4*lane] = s2[lane];
            }
        }
        __syncthreads();

        int c3 = (lane < 4) ? 96 + lane : 96;
        int col[4] = {lane, lane+32, lane+64, c3};
        ull acc[4][4];
        #pragma unroll
        for (int k = 0; k < 4; k++)
            #pragma unroll
            for (int c = 0; c < 4; c++) acc[k][c] = 0ull;

        {
            const ull* WsU = (const ull*)Ws;
            const ull* XsU = (const ull*)Xs;
            const int xbase = wy*4*102;
            ull w[4], x[4], nw[4], nx[4];
            #pragma unroll
            for (int c = 0; c < 4; c++) w[c] = WsU[col[c]*101];
            #pragma unroll
            for (int k = 0; k < 4; k++) x[k] = XsU[xbase + k*102];
            #pragma unroll 1
            for (int dw = 0; dw < 100; dw++){
                int dn = dw + 1;
                #pragma unroll
                for (int c = 0; c < 4; c++) nw[c] = WsU[col[c]*101 + dn];
                #pragma unroll
                for (int k = 0; k < 4; k++) nx[k] = XsU[xbase + k*102 + dn];
                #pragma unroll
                for (int k = 0; k < 4; k++)
                    #pragma unroll
                    for (int c = 0; c < 4; c++)
                        fma2(acc[k][c], x[k], w[c]);
                #pragma unroll
                for (int c = 0; c < 4; c++) w[c] = nw[c];
                #pragma unroll
                for (int k = 0; k < 4; k++) x[k] = nx[k];
            }
        }

        #pragma unroll
        for (int k = 0; k < 4; k++){
            int r = r0 + wy*4 + k;
            if (r >= NN) continue;
            float* go = G + (size_t)r*400 + ob;
            go[col[0]] = unpack_sum(acc[k][0]) + bs[col[0]];
            go[col[1]] = unpack_sum(acc[k][1]) + bs[col[1]];
            go[col[2]] = unpack_sum(acc[k][2]) + bs[col[2]];
            if (lane < 4) go[col[3]] = unpack_sum(acc[k][3]) + bs[col[3]];
        }
    } else {
        // ---- scores + top-10 branch (vectorized) ----
        float* P    = sm;              // [199][102]
        float* qrow = P + 199*102;     // [8][104]
        float* srow = qrow + 8*104;    // [8][200]
        int*   qidx = (int*)(srow + 8*200);  // [200]
        int sid = bid - NGATE;
        int b  = sid & 31;             // sid % 32
        int ty = sid >> 5;             // sid / 32, 0..24
        if (tid < TT) qidx[tid] = question[b*TT + tid];
        __syncthreads();
        int tmax = min(TM - 1, ty*8 + 7);
        int rmax = tmax;
        for (int i = tid; i < rmax*50; i += 256) {
            int s = i / 50, d2 = i - s*50;
            float2 v = ((const float2*)(emb_q + (size_t)qidx[s]*DD))[d2];
            *(float2*)&P[s*102 + 2*d2] = v;
        }
        __syncthreads();
        int t = ty*8 + wy;
        if (t >= TM) return;
        int qv = qidx[t + 1];
        for (int d = lane; d < 50; d += 32)
            *(float2*)&qrow[wy*104 + 2*d] = ((const float2*)(emb_q + (size_t)qv*DD))[d];
        __syncwarp();
        const ull* qrU = (const ull*)qrow + wy*52;
        for (int s = lane; s < t; s += 32) {
            const ull* prU = (const ull*)P + s*51;
            ull acc2 = 0ull;
            #pragma unroll 5
            for (int dw = 0; dw < 50; dw++) fma2(acc2, qrU[dw], prU[dw]);
            srow[wy*200 + s] = unpack_sum(acc2);
        }
        __syncwarp();
        int n = b*TM + t;
        int cnt = min(t, KK);
        for (int sel = 0; sel < KK; sel++) {
            if (sel < cnt) {
                float bv = -3.4e38f; unsigned bi = 0xffffffffu;
                for (int s = lane; s < t; s += 32) {
                    float v = srow[wy*200 + s];
                    if (v > bv) { bv = v; bi = (unsigned)s; }
                }
                #pragma unroll
                for (int off = 16; off; off >>= 1) {
                    float    ov = __shfl_down_sync(0xffffffffu, bv, off);
                    unsigned oi = __shfl_down_sync(0xffffffffu, bi, off);
                    if (ov > bv || (ov == bv && oi < bi)) { bv = ov; bi = oi; }
                }
                bi = __shfl_sync(0xffffffffu, bi, 0);
                if (lane == 0) { topk[n*KK + sel] = (int)bi; srow[wy*200 + bi] = -3.4e38f; }
                __syncwarp();
            } else if (lane == 0) {
                topk[n*KK + sel] = -1;
            }
        }
    }
}

// ---------------- LSTM pointwise + output tail (fused) ----------------
__global__ void lstm_pw_k(const float* __restrict__ G, float* __restrict__ L,
                          float* __restrict__ out) {
    int i = blockIdx.x*blockDim.x + threadIdx.x;
    if (i < BB) out[i*TT] = 0.5f;
    if (i >= NN*DD) return;
    int n = i/DD, d = i - n*DD;
    const float* g = G + (size_t)n*400;
    float gi = g[d], gg = g[200+d], go = g[300+d];
    float val = fsig(go) * ftanh(fsig(gi) * ftanh(gg));
    L[i] = val;
    int b = n / TM, t = n - b*TM;
    if (t == TM-1) out[BB*TT + b*DD + d] = val;
}

// ---------------- fused KT affine + attention + output: 4 n's (44 hist rows) / block ----------------

__global__ __launch_bounds__(256) void ktfinal_k(
    const int* __restrict__ question, const int* __restrict__ skidx,
    const int* __restrict__ skmask, const float* __restrict__ emb_q,
    const float* __restrict__ emb_s, const float* __restrict__ L,
    const int* __restrict__ topk, const float* __restrict__ Wq,
    const float* __restrict__ bq, const float* __restrict__ w_att,
    float* __restrict__ out){
    extern __shared__ float sm[];
    float* Ws  = sm;               // 10200
    float* Xs  = sm + 10200;       // 48*104
    float* bs  = Xs + 48*104;      // 100
    float* w2s = bs + 100;         // 100
    float* qsm = w2s + 100;        // 4*104
    float* ktm = qsm + 4*104;      // 48
    float* gvm = ktm + 48;         // 48
    int tid = threadIdx.x, wy = tid >> 5, lane = tid & 31;
    int n0 = blockIdx.x * 4;

    loadW100(Wq, Ws, tid);
    if (tid < 100) { bs[tid] = bq[tid]; w2s[tid] = w_att[100 + tid]; }

    for (int rr = wy; rr < 48; rr += 8){
        if (lane < 25){
            float4 val = make_float4(0.f,0.f,0.f,0.f);
            if (rr < 44){
                int n = n0 + rr/11, s = rr - (rr/11)*11;
                int b = n / TM, t = n - b*TM;
                int cnt = min(t, KK);
                const float* src = nullptr;
                if (s == 0) src = L + (size_t)n*100;
                else if (s-1 < cnt){
                    int idx = topk[n*KK + s - 1];
                    if (idx > 0) src = L + ((size_t)b*TM + idx)*100;
                }
                if (src) val = ((const float4*)src)[lane];
            }
            *(float4*)&Xs[rr*104 + 4*lane] = val;
        }
    }
    if (wy < 4){
        int n = n0 + wy;
        int b = n / TM, t = n - b*TM;
        int qv = question[b*TT + t + 1];
        if (lane < 25){
            float4 v = ((const float4*)(emb_q + (size_t)qv*100))[lane];
            #pragma unroll
            for (int i = 0; i < 4; i++){
                if (skmask[qv*4 + i] != 0){
                    float4 e = ((const float4*)(emb_s + (size_t)skidx[qv*4 + i]*100))[lane];
                    v.x += e.x; v.y += e.y; v.z += e.z; v.w += e.w;
                }
            }
            *(float4*)&qsm[wy*104 + 4*lane] = v;
        }
    }
    __syncthreads();

    int c3 = (lane < 4) ? 96 + lane : 96;
    int col[4] = {lane, lane+32, lane+64, c3};
    ull acc[6][4];
    #pragma unroll
    for (int k = 0; k < 6; k++)
        #pragma unroll
        for (int c = 0; c < 4; c++) acc[k][c] = 0ull;
    core100p<6>(Ws, Xs, wy, col, acc);

    #pragma unroll
    for (int k = 0; k < 6; k++){
        int rr = wy*6 + k;
        if (rr >= 44) continue;
        int nl = rr / 11;
        float o0 = ftanh(unpack_sum(acc[k][0]) + bs[col[0]]);
        float o1 = ftanh(unpack_sum(acc[k][1]) + bs[col[1]]);
        float o2 = ftanh(unpack_sum(acc[k][2]) + bs[col[2]]);
        float o3 = ftanh(unpack_sum(acc[k][3]) + bs[col[3]]);
        float v = o0*w2s[col[0]] + o1*w2s[col[1]] + o2*w2s[col[2]];
        float g = Xs[rr*104+col[0]]*qsm[nl*104+col[0]]
                + Xs[rr*104+col[1]]*qsm[nl*104+col[1]]
                + Xs[rr*104+col[2]]*qsm[nl*104+col[2]];
        if (lane < 4){
            v += o3*w2s[col[3]];
            g += Xs[rr*104+col[3]]*qsm[nl*104+col[3]];
        }
        #pragma unroll
        for (int off = 16; off; off >>= 1){
            v += __shfl_down_sync(0xffffffffu, v, off);
            g += __shfl_down_sync(0xffffffffu, g, off);
        }
        if (lane == 0){ ktm[rr] = v; gvm[rr] = g; }
    }
    __syncthreads();

    if (tid < 4){
        int n = n0 + tid;
        int b = n / TM, t = n - b*TM;
        int cnt = min(t, KK);
        float m = -3.4e38f;
        for (int s = 0; s <= cnt; s++){ float v = ktm[tid*11 + s]; if (v > m) m = v; }
        float Z = 0.f, P = 0.f;
        for (int s = 0; s <= cnt; s++){
            float e = __expf(ktm[tid*11 + s] - m);
            Z += e; P += e*gvm[tid*11 + s];
        }
        out[b*TT + 1 + t] = fsig(__fdividef(P, Z));
    }
}

// ---------------- launch ----------------

extern "C" void kernel_launch(void* const* d_in, const int* in_sizes, int n_in,
                              void* d_out, int out_size) {
    const int*   question = (const int*)d_in[0];
    const int*   response = (const int*)d_in[1];
    const int*   maskp    = (const int*)d_in[2];
    const int*   q_nb     = (const int*)d_in[3];
    const int*   s_nb     = (const int*)d_in[4];
    const int*   skidx    = (const int*)d_in[5];
    const int*   skmask   = (const int*)d_in[6];
    const float* emb_q    = (const float*)d_in[7];
    const float* emb_s    = (const float*)d_in[8];
    const float* emb_r    = (const float*)d_in[9];
    const float* Wih      = (const float*)d_in[10];
    const float* lb       = (const float*)d_in[11];
    const float* aggW     = (const float*)d_in[12];
    const float* aggb     = (const float*)d_in[13];
    const float* aggLW    = (const float*)d_in[14];
    const float* aggLb    = (const float*)d_in[15];
    const float* Wq       = (const float*)d_in[16];
    const float* bq       = (const float*)d_in[17];
    const float* w_att    = (const float*)d_in[20];
    float* out = (float*)d_out;

    float* buf = nullptr; int* topk = nullptr;
    cudaGetSymbolAddress((void**)&buf,  g_buf);
    cudaGetSymbolAddress((void**)&topk, g_topk);

    float* pE2  = buf + OFF_E2;
    float* pE1  = buf + OFF_E1;
    float* pE0a = buf + OFF_E0A;
    float* pE1b = buf + OFF_E1B;
    float* pE0b = buf + OFF_E0B;
    float* pAGG = buf + OFF_AGG;
    float* pL   = buf + OFF_L;
    float* pG   = buf + OFF_G;

    const int AFF_SMEM = (10200 + 48*104 + 100)*4;
    const int D_SMEM   = (10200 + 24*104 + 100)*4;
    const int KTF_SMEM = (10200 + 48*104 + 100 + 100 + 4*104 + 48 + 48)*4;
    const int GAT_SMEM = (20200 + 32*204 + 100)*4;                       // 107312
    const int SCO_SMEM = (199*102 + 8*104 + 8*200 + 200)*4;              // 91624
    const int GSC_SMEM = (GAT_SMEM > SCO_SMEM) ? GAT_SMEM : SCO_SMEM;
    cudaFuncSetAttribute(stageB_k,      cudaFuncAttributeMaxDynamicSharedMemorySize, AFF_SMEM);
    cudaFuncSetAttribute(stageC_k,      cudaFuncAttributeMaxDynamicSharedMemorySize, AFF_SMEM);
    cudaFuncSetAttribute(stageD_k,      cudaFuncAttributeMaxDynamicSharedMemorySize, D_SMEM);
    cudaFuncSetAttribute(gatesScores_k, cudaFuncAttributeMaxDynamicSharedMemorySize, GSC_SMEM);
    cudaFuncSetAttribute(ktfinal_k,     cudaFuncAttributeMaxDynamicSharedMemorySize, KTF_SMEM);

    stageB_k<<<NB0+NB1+NB2, 256, AFF_SMEM>>>(question, q_nb, s_nb, emb_q, emb_s,
                                             aggW, aggb, pE2, pE1, pE0a);
    stageC_k<<<NB1+NB2, 256, AFF_SMEM>>>(pE1, pE2, pE0a, aggW, aggb, pE1b, pE0b);
    stageD_k<<<NBD, 256, D_SMEM>>>(pE0b, pE1b, aggW, aggb, aggLW, aggLb, pAGG);

    gatesScores_k<<<NGATE+NSCOR, 256, GSC_SMEM>>>(question, response, maskp, emb_q, emb_r,
                                                  pAGG, Wih, lb, pG, topk);
    lstm_pw_k<<<(NN*DD + 255)/256, 256>>>(pG, pL, out);

    ktfinal_k<<<NN/4, 256, KTF_SMEM>>>(question, skidx, skmask, emb_q, emb_s,
                                       pL, topk, Wq, bq, w_att, out);
}

// round 14
// speedup vs baseline: 2.0994x; 1.6050x over previous
#include <cuda_runtime.h>
#include <math.h>

#define BB 32
#define TT 200
#define TM 199
#define NN (BB*TM)        // 6368
#define DD 100
#define KK 10
#define NE2 4800          // unique (sk,s) pairs = NUM_S*NS
#define NE1 1200          // unique skills = NUM_S

#define MB0 100           // NE2/48
#define MB1 25            // NE1/48
#define NB2 133           // ceil(NN/48)
#define NBD 266           // ceil(NN/24)
#define NGATE 597
#define NSCOR 800

typedef unsigned long long ull;

// ---------------- scratch ----------------
__device__ float g_buf[5814400];
__device__ int   g_topk[NN*KK];

static constexpr size_t OFF_E2P = 0;          // NE2*100 = 480000
static constexpr size_t OFF_E1T = 480000;     // NE1*100 = 120000
static constexpr size_t OFF_E0A = 600000;     // NN*100 = 636800
static constexpr size_t OFF_E1B = 1236800;    // NE1*100
static constexpr size_t OFF_E0B = 1356800;    // NN*100
static constexpr size_t OFF_AGG = 1993600;    // NN*100
static constexpr size_t OFF_L   = 2630400;    // NN*100
static constexpr size_t OFF_G   = 3267200;    // NN*400

// ---------------- helpers ----------------
__device__ __forceinline__ void fma2(ull& a, ull x, ull w){
    asm("fma.rn.f32x2 %0, %1, %2, %0;" : "+l"(a) : "l"(x), "l"(w));
}
__device__ __forceinline__ float unpack_sum(ull a){
    float lo = __int_as_float((int)(unsigned int)a);
    float hi = __int_as_float((int)(unsigned int)(a >> 32));
    return lo + hi;
}
__device__ __forceinline__ float ftanh(float x){
    float e = __expf(2.f*x);
    return 1.f - __fdividef(2.f, e + 1.f);
}
__device__ __forceinline__ float fsig(float x){
    return __fdividef(1.f, 1.f + __expf(-x));
}

// load 100x100 W into smem pitch 102 (51 ull words; conflict-free LDS.64)
__device__ __forceinline__ void loadW100(const float* __restrict__ W, float* Ws, int tid){
    for (int j = tid; j < 2500; j += 256){
        float4 v = ((const float4*)W)[j];
        int b4 = 4*j; int o = b4/100; int d = b4 - o*100;
        float2* ws = (float2*)&Ws[o*102 + d];
        ws[0] = make_float2(v.x, v.y);
        ws[1] = make_float2(v.z, v.w);
    }
}

// Software-pipelined KR-rows-per-thread 100-d FFMA core.
template<int KR>
__device__ __forceinline__ void core100p(const float* Ws, const float* Xs, int wy,
                                         const int* col, ull (*acc)[4]){
    const ull* WsU = (const ull*)Ws;
    const ull* XsU = (const ull*)Xs;
    const int xbase = wy*KR*52;
    ull w[4], x[KR], nw[4], nx[KR];
    #pragma unroll
    for (int c = 0; c < 4; c++) w[c] = WsU[col[c]*51];
    #pragma unroll
    for (int k = 0; k < KR; k++) x[k] = XsU[xbase + k*52];
    #pragma unroll 1
    for (int dw = 0; dw < 50; dw++){
        int dn = dw + 1;
        #pragma unroll
        for (int c = 0; c < 4; c++) nw[c] = WsU[col[c]*51 + dn];
        #pragma unroll
        for (int k = 0; k < KR; k++) nx[k] = XsU[xbase + k*52 + dn];
        #pragma unroll
        for (int k = 0; k < KR; k++)
            #pragma unroll
            for (int c = 0; c < 4; c++)
                fma2(acc[k][c], x[k], w[c]);
        #pragma unroll
        for (int c = 0; c < 4; c++) w[c] = nw[c];
        #pragma unroll
        for (int k = 0; k < KR; k++) x[k] = nx[k];
    }
}

// ---------------- stage B: deduped gather + affine ----------------
// seg0: E2P[j], j in [0,4800): q2 = s_nb[j]; base emb_q[q2], kids emb_s[q_nb[q2]].
// seg1: E1T[sk], sk in [0,1200): base emb_s[sk], kids emb_q[s_nb[sk]].
// seg2: E0a[n], n in [0,NN): q = question; base emb_q[q], kids emb_s[q_nb[q]].

__global__ __launch_bounds__(256) void stageB_k(
    const int* __restrict__ question, const int* __restrict__ q_nb,
    const int* __restrict__ s_nb, const float* __restrict__ emb_q,
    const float* __restrict__ emb_s, const float* __restrict__ aggW,
    const float* __restrict__ aggb, float* __restrict__ E2P,
    float* __restrict__ E1T, float* __restrict__ E0){
    extern __shared__ float sm[];
    float* Ws = sm;            // 10200
    float* Xs = sm + 10200;    // 48*104
    float* bs = Xs + 48*104;   // 100
    int tid = threadIdx.x, wy = tid >> 5, lane = tid & 31;
    int bid = blockIdx.x;

    int seg, r0, R; const float* W; const float* bias; float* Y;
    if (bid < MB0)            { seg=0; r0=bid*48;           R=NE2; W=aggW+20000; bias=aggb+200; Y=E2P; }
    else if (bid < MB0+MB1)   { seg=1; r0=(bid-MB0)*48;     R=NE1; W=aggW+10000; bias=aggb+100; Y=E1T; }
    else                      { seg=2; r0=(bid-MB0-MB1)*48; R=NN;  W=aggW;       bias=aggb;     Y=E0; }

    loadW100(W, Ws, tid);
    if (tid < 100) bs[tid] = bias[tid];

    for (int rr = wy; rr < 48; rr += 8){
        if (lane < 25){
            int r = r0 + rr;
            float4 val = make_float4(0.f,0.f,0.f,0.f);
            if (r < R){
                const float* basep; const int* nb; const float* tbl;
                if (seg == 0){
                    int q2 = s_nb[r];
                    basep = emb_q + (size_t)q2*DD; nb = q_nb + q2*4; tbl = emb_s;
                } else if (seg == 1){
                    basep = emb_s + (size_t)r*DD; nb = s_nb + r*4; tbl = emb_q;
                } else {
                    int b = r / TM, t = r - b*TM;
                    int q = question[b*TT + t];
                    basep = emb_q + (size_t)q*DD; nb = q_nb + q*4; tbl = emb_s;
                }
                int i0 = nb[0], i1 = nb[1], i2 = nb[2], i3 = nb[3];
                float4 bb = ((const float4*)basep)[lane];
                float4 a = ((const float4*)(tbl + (size_t)i0*DD))[lane];
                float4 c = ((const float4*)(tbl + (size_t)i1*DD))[lane];
                float4 d = ((const float4*)(tbl + (size_t)i2*DD))[lane];
                float4 e = ((const float4*)(tbl + (size_t)i3*DD))[lane];
                val.x = bb.x + 0.25f*(a.x+c.x+d.x+e.x);
                val.y = bb.y + 0.25f*(a.y+c.y+d.y+e.y);
                val.z = bb.z + 0.25f*(a.z+c.z+d.z+e.z);
                val.w = bb.w + 0.25f*(a.w+c.w+d.w+e.w);
            }
            *(float4*)&Xs[rr*104 + 4*lane] = val;
        }
    }
    __syncthreads();

    int c3 = (lane < 4) ? 96 + lane : 96;
    int col[4] = {lane, lane+32, lane+64, c3};
    ull acc[6][4];
    #pragma unroll
    for (int k = 0; k < 6; k++)
        #pragma unroll
        for (int c = 0; c < 4; c++) acc[k][c] = 0ull;
    core100p<6>(Ws, Xs, wy, col, acc);

    #pragma unroll
    for (int k = 0; k < 6; k++){
        int r = r0 + wy*6 + k;
        if (r >= R) continue;
        float* yo = Y + (size_t)r*100;
        yo[col[0]] = ftanh(unpack_sum(acc[k][0]) + bs[col[0]]);
        yo[col[1]] = ftanh(unpack_sum(acc[k][1]) + bs[col[1]]);
        yo[col[2]] = ftanh(unpack_sum(acc[k][2]) + bs[col[2]]);
        if (lane < 4) yo[col[3]] = ftanh(unpack_sum(acc[k][3]) + bs[col[3]]);
    }
}

// ---------------- stage C ----------------
// seg1 (bid<MB1): E1bT[sk] = tanh((E1T[sk] + 0.25*sum E2P[sk*4+s]) @ W1 + b1) — kids contiguous.
// seg2: E0b[n] = tanh((E0a[n] + 0.25*sum_k E1T[q_nb[q*4+k]]) @ W0 + b0) — kids gathered.

__global__ __launch_bounds__(256) void stageC_k(
    const int* __restrict__ question, const int* __restrict__ q_nb,
    const float* __restrict__ E1T, const float* __restrict__ E2P,
    const float* __restrict__ E0a,
    const float* __restrict__ aggW, const float* __restrict__ aggb,
    float* __restrict__ E1bT, float* __restrict__ E0b){
    extern __shared__ float sm[];
    float* Ws = sm;
    float* Xs = sm + 10200;
    float* bs = Xs + 48*104;
    int tid = threadIdx.x, wy = tid >> 5, lane = tid & 31;
    int bid = blockIdx.x;

    int seg, r0, R; const float* W; const float* bias; float* Y;
    if (bid < MB1){ seg=1; r0=bid*48;        R=NE1; W=aggW+10000; bias=aggb+100; Y=E1bT; }
    else          { seg=2; r0=(bid-MB1)*48;  R=NN;  W=aggW;       bias=aggb;     Y=E0b; }

    loadW100(W, Ws, tid);
    if (tid < 100) bs[tid] = bias[tid];

    for (int rr = wy; rr < 48; rr += 8){
        if (lane < 25){
            int r = r0 + rr;
            float4 val = make_float4(0.f,0.f,0.f,0.f);
            if (r < R){
                float4 a, c, d4, e, bb;
                if (seg == 1){
                    const float4* kp = (const float4*)(E2P + (size_t)r*400);
                    a = kp[lane]; c = kp[25+lane]; d4 = kp[50+lane]; e = kp[75+lane];
                    bb = ((const float4*)(E1T + (size_t)r*100))[lane];
                } else {
                    int b = r / TM, t = r - b*TM;
                    int q = question[b*TT + t];
                    const int* nb = q_nb + q*4;
                    a  = ((const float4*)(E1T + (size_t)nb[0]*100))[lane];
                    c  = ((const float4*)(E1T + (size_t)nb[1]*100))[lane];
                    d4 = ((const float4*)(E1T + (size_t)nb[2]*100))[lane];
                    e  = ((const float4*)(E1T + (size_t)nb[3]*100))[lane];
                    bb = ((const float4*)(E0a + (size_t)r*100))[lane];
                }
                val.x = bb.x + 0.25f*(a.x+c.x+d4.x+e.x);
                val.y = bb.y + 0.25f*(a.y+c.y+d4.y+e.y);
                val.z = bb.z + 0.25f*(a.z+c.z+d4.z+e.z);
                val.w = bb.w + 0.25f*(a.w+c.w+d4.w+e.w);
            }
            *(float4*)&Xs[rr*104 + 4*lane] = val;
        }
    }
    __syncthreads();

    int c3 = (lane < 4) ? 96 + lane : 96;
    int col[4] = {lane, lane+32, lane+64, c3};
    ull acc[6][4];
    #pragma unroll
    for (int k = 0; k < 6; k++)
        #pragma unroll
        for (int c = 0; c < 4; c++) acc[k][c] = 0ull;
    core100p<6>(Ws, Xs, wy, col, acc);

    #pragma unroll
    for (int k = 0; k < 6; k++){
        int r = r0 + wy*6 + k;
        if (r >= R) continue;
        float* yo = Y + (size_t)r*100;
        yo[col[0]] = ftanh(unpack_sum(acc[k][0]) + bs[col[0]]);
        yo[col[1]] = ftanh(unpack_sum(acc[k][1]) + bs[col[1]]);
        yo[col[2]] = ftanh(unpack_sum(acc[k][2]) + bs[col[2]]);
        if (lane < 4) yo[col[3]] = ftanh(unpack_sum(acc[k][3]) + bs[col[3]]);
    }
}

// ---------------- stage D: chained double affine, 24-row tiles; kids gathered from E1bT ----------------

__global__ __launch_bounds__(256) void stageD_k(
    const int* __restrict__ question, const int* __restrict__ q_nb,
    const float* __restrict__ E0b, const float* __restrict__ E1bT,
    const float* __restrict__ aggW, const float* __restrict__ aggb,
    const float* __restrict__ aggLW, const float* __restrict__ aggLb,
    float* __restrict__ AGG){
    extern __shared__ float sm[];
    float* Ws = sm;            // 10200
    float* Xs = sm + 10200;    // 24*104
    float* bs = Xs + 24*104;   // 100
    int tid = threadIdx.x, wy = tid >> 5, lane = tid & 31;
    int r0 = blockIdx.x * 24;

    loadW100(aggW, Ws, tid);
    if (tid < 100) bs[tid] = aggb[tid];

    for (int rr = wy; rr < 24; rr += 8){
        if (lane < 25){
            int r = r0 + rr;
            float4 val = make_float4(0.f,0.f,0.f,0.f);
            if (r < NN){
                int b = r / TM, t = r - b*TM;
                int q = question[b*TT + t];
                const int* nb = q_nb + q*4;
                float4 a  = ((const float4*)(E1bT + (size_t)nb[0]*100))[lane];
                float4 c  = ((const float4*)(E1bT + (size_t)nb[1]*100))[lane];
                float4 d4 = ((const float4*)(E1bT + (size_t)nb[2]*100))[lane];
                float4 e  = ((const float4*)(E1bT + (size_t)nb[3]*100))[lane];
                float4 bb = ((const float4*)(E0b + (size_t)r*100))[lane];
                val.x = bb.x + 0.25f*(a.x+c.x+d4.x+e.x);
                val.y = bb.y + 0.25f*(a.y+c.y+d4.y+e.y);
                val.z = bb.z + 0.25f*(a.z+c.z+d4.z+e.z);
                val.w = bb.w + 0.25f*(a.w+c.w+d4.w+e.w);
            }
            *(float4*)&Xs[rr*104 + 4*lane] = val;
        }
    }
    __syncthreads();

    int c3 = (lane < 4) ? 96 + lane : 96;
    int col[4] = {lane, lane+32, lane+64, c3};
    ull acc[3][4];
    #pragma unroll
    for (int k = 0; k < 3; k++)
        #pragma unroll
        for (int c = 0; c < 4; c++) acc[k][c] = 0ull;
    core100p<3>(Ws, Xs, wy, col, acc);

    #pragma unroll
    for (int k = 0; k < 3; k++){
        int rr = wy*3 + k;
        int r = r0 + rr;
        if (r >= NN) continue;
        Xs[rr*104 + col[0]] = ftanh(unpack_sum(acc[k][0]) + bs[col[0]]);
        Xs[rr*104 + col[1]] = ftanh(unpack_sum(acc[k][1]) + bs[col[1]]);
        Xs[rr*104 + col[2]] = ftanh(unpack_sum(acc[k][2]) + bs[col[2]]);
        if (lane < 4) Xs[rr*104 + col[3]] = ftanh(unpack_sum(acc[k][3]) + bs[col[3]]);
    }
    __syncthreads();

    loadW100(aggLW, Ws, tid);
    if (tid < 100) bs[tid] = aggLb[tid];
    __syncthreads();

    #pragma unroll
    for (int k = 0; k < 3; k++)
        #pragma unroll
        for (int c = 0; c < 4; c++) acc[k][c] = 0ull;
    core100p<3>(Ws, Xs, wy, col, acc);

    #pragma unroll
    for (int k = 0; k < 3; k++){
        int r = r0 + wy*3 + k;
        if (r >= NN) continue;
        float* yo = AGG + (size_t)r*100;
        yo[col[0]] = ftanh(unpack_sum(acc[k][0]) + bs[col[0]]);
        yo[col[1]] = ftanh(unpack_sum(acc[k][1]) + bs[col[1]]);
        yo[col[2]] = ftanh(unpack_sum(acc[k][2]) + bs[col[2]]);
        if (lane < 4) yo[col[3]] = ftanh(unpack_sum(acc[k][3]) + bs[col[3]]);
    }
}

// ---------------- FUSED: LSTM gates (blocks 0..596) + scores/top-10 (blocks 597..1396) ----------------

__global__ __launch_bounds__(256) void gatesScores_k(
    const int* __restrict__ question, const int* __restrict__ response,
    const int* __restrict__ maskp, const float* __restrict__ emb_q,
    const float* __restrict__ emb_r, const float* __restrict__ AGG,
    const float* __restrict__ Wih, const float* __restrict__ lb,
    float* __restrict__ G, int* __restrict__ topk){
    extern __shared__ float sm[];
    int tid = threadIdx.x, wy = tid >> 5, lane = tid & 31;
    int bid = blockIdx.x;

    if (bid < NGATE){
        float* Ws = sm;             // 100 x 202
        float* Xs = sm + 20200;     // 32 x 204
        float* bs = Xs + 32*204;    // 100
        int gy = bid / 199;
        int bx = bid - gy*199;
        int ob = (gy == 0) ? 0 : (gy + 1)*100;   // 0, 200, 300
        const float* W = Wih + (size_t)ob*200;

        for (int j = tid; j < 5000; j += 256){
            float4 v = ((const float4*)W)[j];
            int b4 = 4*j; int o = b4/200; int d = b4 - o*200;
            float2* ws = (float2*)&Ws[o*202 + d];
            ws[0] = make_float2(v.x, v.y);
            ws[1] = make_float2(v.z, v.w);
        }
        if (tid < 100) bs[tid] = lb[ob + tid];

        int r0 = bx * 32;
        for (int rr = wy; rr < 32; rr += 8){
            if (lane < 25){
                int r = r0 + rr;
                int b = r / TM, t = r - b*TM;
                int q   = question[b*TT + t];
                int m   = maskp[b*TT + t];
                int rsp = response[b*TT + t];
                const float4* s1 = (const float4*)((m == 1) ? (AGG + (size_t)r*100)
                                                            : (emb_q + (size_t)q*100));
                const float4* s2 = (const float4*)(emb_r + (size_t)rsp*100);
                *(float4*)&Xs[rr*204 + 4*lane]       = s1[lane];
                *(float4*)&Xs[rr*204 + 100 + 4*lane] = s2[lane];
            }
        }
        __syncthreads();

        int c3 = (lane < 4) ? 96 + lane : 96;
        int col[4] = {lane, lane+32, lane+64, c3};
        ull acc[4][4];
        #pragma unroll
        for (int k = 0; k < 4; k++)
            #pragma unroll
            for (int c = 0; c < 4; c++) acc[k][c] = 0ull;

        {
            const ull* WsU = (const ull*)Ws;
            const ull* XsU = (const ull*)Xs;
            const int xbase = wy*4*102;
            ull w[4], x[4], nw[4], nx[4];
            #pragma unroll
            for (int c = 0; c < 4; c++) w[c] = WsU[col[c]*101];
            #pragma unroll
            for (int k = 0; k < 4; k++) x[k] = XsU[xbase + k*102];
            #pragma unroll 1
            for (int dw = 0; dw < 100; dw++){
                int dn = dw + 1;
                #pragma unroll
                for (int c = 0; c < 4; c++) nw[c] = WsU[col[c]*101 + dn];
                #pragma unroll
                for (int k = 0; k < 4; k++) nx[k] = XsU[xbase + k*102 + dn];
                #pragma unroll
                for (int k = 0; k < 4; k++)
                    #pragma unroll
                    for (int c = 0; c < 4; c++)
                        fma2(acc[k][c], x[k], w[c]);
                #pragma unroll
                for (int c = 0; c < 4; c++) w[c] = nw[c];
                #pragma unroll
                for (int k = 0; k < 4; k++) x[k] = nx[k];
            }
        }

        #pragma unroll
        for (int k = 0; k < 4; k++){
            int r = r0 + wy*4 + k;
            if (r >= NN) continue;
            float* go = G + (size_t)r*400 + ob;
            go[col[0]] = unpack_sum(acc[k][0]) + bs[col[0]];
            go[col[1]] = unpack_sum(acc[k][1]) + bs[col[1]];
            go[col[2]] = unpack_sum(acc[k][2]) + bs[col[2]];
            if (lane < 4) go[col[3]] = unpack_sum(acc[k][3]) + bs[col[3]];
        }
    } else {
        float* P    = sm;              // [199][102]
        float* qrow = P + 199*102;     // [8][104]
        float* srow = qrow + 8*104;    // [8][200]
        int*   qidx = (int*)(srow + 8*200);  // [200]
        int sid = bid - NGATE;
        int b  = sid & 31;
        int ty = sid >> 5;
        if (tid < TT) qidx[tid] = question[b*TT + tid];
        __syncthreads();
        int tmax = min(TM - 1, ty*8 + 7);
        int rmax = tmax;
        for (int i = tid; i < rmax*50; i += 256) {
            int s = i / 50, d2 = i - s*50;
            float2 v = ((const float2*)(emb_q + (size_t)qidx[s]*DD))[d2];
            *(float2*)&P[s*102 + 2*d2] = v;
        }
        __syncthreads();
        int t = ty*8 + wy;
        if (t >= TM) return;
        int qv = qidx[t + 1];
        for (int d = lane; d < 50; d += 32)
            *(float2*)&qrow[wy*104 + 2*d] = ((const float2*)(emb_q + (size_t)qv*DD))[d];
        __syncwarp();
        const ull* qrU = (const ull*)qrow + wy*52;
        for (int s = lane; s < t; s += 32) {
            const ull* prU = (const ull*)P + s*51;
            ull acc2 = 0ull;
            #pragma unroll 5
            for (int dw = 0; dw < 50; dw++) fma2(acc2, qrU[dw], prU[dw]);
            srow[wy*200 + s] = unpack_sum(acc2);
        }
        __syncwarp();
        int n = b*TM + t;
        int cnt = min(t, KK);
        for (int sel = 0; sel < KK; sel++) {
            if (sel < cnt) {
                float bv = -3.4e38f; unsigned bi = 0xffffffffu;
                for (int s = lane; s < t; s += 32) {
                    float v = srow[wy*200 + s];
                    if (v > bv) { bv = v; bi = (unsigned)s; }
                }
                #pragma unroll
                for (int off = 16; off; off >>= 1) {
                    float    ov = __shfl_down_sync(0xffffffffu, bv, off);
                    unsigned oi = __shfl_down_sync(0xffffffffu, bi, off);
                    if (ov > bv || (ov == bv && oi < bi)) { bv = ov; bi = oi; }
                }
                bi = __shfl_sync(0xffffffffu, bi, 0);
                if (lane == 0) { topk[n*KK + sel] = (int)bi; srow[wy*200 + bi] = -3.4e38f; }
                __syncwarp();
            } else if (lane == 0) {
                topk[n*KK + sel] = -1;
            }
        }
    }
}

// ---------------- LSTM pointwise + output tail (fused) ----------------
__global__ void lstm_pw_k(const float* __restrict__ G, float* __restrict__ L,
                          float* __restrict__ out) {
    int i = blockIdx.x*blockDim.x + threadIdx.x;
    if (i < BB) out[i*TT] = 0.5f;
    if (i >= NN*DD) return;
    int n = i/DD, d = i - n*DD;
    const float* g = G + (size_t)n*400;
    float gi = g[d], gg = g[200+d], go = g[300+d];
    float val = fsig(go) * ftanh(fsig(gi) * ftanh(gg));
    L[i] = val;
    int b = n / TM, t = n - b*TM;
    if (t == TM-1) out[BB*TT + b*DD + d] = val;
}

// ---------------- fused KT affine + attention + output: 4 n's (44 hist rows) / block ----------------

__global__ __launch_bounds__(256) void ktfinal_k(
    const int* __restrict__ question, const int* __restrict__ skidx,
    const int* __restrict__ skmask, const float* __restrict__ emb_q,
    const float* __restrict__ emb_s, const float* __restrict__ L,
    const int* __restrict__ topk, const float* __restrict__ Wq,
    const float* __restrict__ bq, const float* __restrict__ w_att,
    float* __restrict__ out){
    extern __shared__ float sm[];
    float* Ws  = sm;               // 10200
    float* Xs  = sm + 10200;       // 48*104
    float* bs  = Xs + 48*104;      // 100
    float* w2s = bs + 100;         // 100
    float* qsm = w2s + 100;        // 4*104
    float* ktm = qsm + 4*104;      // 48
    float* gvm = ktm + 48;         // 48
    int tid = threadIdx.x, wy = tid >> 5, lane = tid & 31;
    int n0 = blockIdx.x * 4;

    loadW100(Wq, Ws, tid);
    if (tid < 100) { bs[tid] = bq[tid]; w2s[tid] = w_att[100 + tid]; }

    for (int rr = wy; rr < 48; rr += 8){
        if (lane < 25){
            float4 val = make_float4(0.f,0.f,0.f,0.f);
            if (rr < 44){
                int n = n0 + rr/11, s = rr - (rr/11)*11;
                int b = n / TM, t = n - b*TM;
                int cnt = min(t, KK);
                const float* src = nullptr;
                if (s == 0) src = L + (size_t)n*100;
                else if (s-1 < cnt){
                    int idx = topk[n*KK + s - 1];
                    if (idx > 0) src = L + ((size_t)b*TM + idx)*100;
                }
                if (src) val = ((const float4*)src)[lane];
            }
            *(float4*)&Xs[rr*104 + 4*lane] = val;
        }
    }
    if (wy < 4){
        int n = n0 + wy;
        int b = n / TM, t = n - b*TM;
        int qv = question[b*TT + t + 1];
        if (lane < 25){
            float4 v = ((const float4*)(emb_q + (size_t)qv*100))[lane];
            #pragma unroll
            for (int i = 0; i < 4; i++){
                if (skmask[qv*4 + i] != 0){
                    float4 e = ((const float4*)(emb_s + (size_t)skidx[qv*4 + i]*100))[lane];
                    v.x += e.x; v.y += e.y; v.z += e.z; v.w += e.w;
                }
            }
            *(float4*)&qsm[wy*104 + 4*lane] = v;
        }
    }
    __syncthreads();

    int c3 = (lane < 4) ? 96 + lane : 96;
    int col[4] = {lane, lane+32, lane+64, c3};
    ull acc[6][4];
    #pragma unroll
    for (int k = 0; k < 6; k++)
        #pragma unroll
        for (int c = 0; c < 4; c++) acc[k][c] = 0ull;
    core100p<6>(Ws, Xs, wy, col, acc);

    #pragma unroll
    for (int k = 0; k < 6; k++){
        int rr = wy*6 + k;
        if (rr >= 44) continue;
        int nl = rr / 11;
        float o0 = ftanh(unpack_sum(acc[k][0]) + bs[col[0]]);
        float o1 = ftanh(unpack_sum(acc[k][1]) + bs[col[1]]);
        float o2 = ftanh(unpack_sum(acc[k][2]) + bs[col[2]]);
        float o3 = ftanh(unpack_sum(acc[k][3]) + bs[col[3]]);
        float v = o0*w2s[col[0]] + o1*w2s[col[1]] + o2*w2s[col[2]];
        float g = Xs[rr*104+col[0]]*qsm[nl*104+col[0]]
                + Xs[rr*104+col[1]]*qsm[nl*104+col[1]]
                + Xs[rr*104+col[2]]*qsm[nl*104+col[2]];
        if (lane < 4){
            v += o3*w2s[col[3]];
            g += Xs[rr*104+col[3]]*qsm[nl*104+col[3]];
        }
        #pragma unroll
        for (int off = 16; off; off >>= 1){
            v += __shfl_down_sync(0xffffffffu, v, off);
            g += __shfl_down_sync(0xffffffffu, g, off);
        }
        if (lane == 0){ ktm[rr] = v; gvm[rr] = g; }
    }
    __syncthreads();

    if (tid < 4){
        int n = n0 + tid;
        int b = n / TM, t = n - b*TM;
        int cnt = min(t, KK);
        float m = -3.4e38f;
        for (int s = 0; s <= cnt; s++){ float v = ktm[tid*11 + s]; if (v > m) m = v; }
        float Z = 0.f, P = 0.f;
        for (int s = 0; s <= cnt; s++){
            float e = __expf(ktm[tid*11 + s] - m);
            Z += e; P += e*gvm[tid*11 + s];
        }
        out[b*TT + 1 + t] = fsig(__fdividef(P, Z));
    }
}

// ---------------- launch ----------------

extern "C" void kernel_launch(void* const* d_in, const int* in_sizes, int n_in,
                              void* d_out, int out_size) {
    const int*   question = (const int*)d_in[0];
    const int*   response = (const int*)d_in[1];
    const int*   maskp    = (const int*)d_in[2];
    const int*   q_nb     = (const int*)d_in[3];
    const int*   s_nb     = (const int*)d_in[4];
    const int*   skidx    = (const int*)d_in[5];
    const int*   skmask   = (const int*)d_in[6];
    const float* emb_q    = (const float*)d_in[7];
    const float* emb_s    = (const float*)d_in[8];
    const float* emb_r    = (const float*)d_in[9];
    const float* Wih      = (const float*)d_in[10];
    const float* lb       = (const float*)d_in[11];
    const float* aggW     = (const float*)d_in[12];
    const float* aggb     = (const float*)d_in[13];
    const float* aggLW    = (const float*)d_in[14];
    const float* aggLb    = (const float*)d_in[15];
    const float* Wq       = (const float*)d_in[16];
    const float* bq       = (const float*)d_in[17];
    const float* w_att    = (const float*)d_in[20];
    float* out = (float*)d_out;

    float* buf = nullptr; int* topk = nullptr;
    cudaGetSymbolAddress((void**)&buf,  g_buf);
    cudaGetSymbolAddress((void**)&topk, g_topk);

    float* pE2P = buf + OFF_E2P;
    float* pE1T = buf + OFF_E1T;
    float* pE0a = buf + OFF_E0A;
    float* pE1b = buf + OFF_E1B;
    float* pE0b = buf + OFF_E0B;
    float* pAGG = buf + OFF_AGG;
    float* pL   = buf + OFF_L;
    float* pG   = buf + OFF_G;

    const int AFF_SMEM = (10200 + 48*104 + 100)*4;
    const int D_SMEM   = (10200 + 24*104 + 100)*4;
    const int KTF_SMEM = (10200 + 48*104 + 100 + 100 + 4*104 + 48 + 48)*4;
    const int GAT_SMEM = (20200 + 32*204 + 100)*4;
    const int SCO_SMEM = (199*102 + 8*104 + 8*200 + 200)*4;
    const int GSC_SMEM = (GAT_SMEM > SCO_SMEM) ? GAT_SMEM : SCO_SMEM;
    cudaFuncSetAttribute(stageB_k,      cudaFuncAttributeMaxDynamicSharedMemorySize, AFF_SMEM);
    cudaFuncSetAttribute(stageC_k,      cudaFuncAttributeMaxDynamicSharedMemorySize, AFF_SMEM);
    cudaFuncSetAttribute(stageD_k,      cudaFuncAttributeMaxDynamicSharedMemorySize, D_SMEM);
    cudaFuncSetAttribute(gatesScores_k, cudaFuncAttributeMaxDynamicSharedMemorySize, GSC_SMEM);
    cudaFuncSetAttribute(ktfinal_k,     cudaFuncAttributeMaxDynamicSharedMemorySize, KTF_SMEM);

    stageB_k<<<MB0+MB1+NB2, 256, AFF_SMEM>>>(question, q_nb, s_nb, emb_q, emb_s,
                                             aggW, aggb, pE2P, pE1T, pE0a);
    stageC_k<<<MB1+NB2, 256, AFF_SMEM>>>(question, q_nb, pE1T, pE2P, pE0a,
                                         aggW, aggb, pE1b, pE0b);
    stageD_k<<<NBD, 256, D_SMEM>>>(question, q_nb, pE0b, pE1b,
                                   aggW, aggb, aggLW, aggLb, pAGG);

    gatesScores_k<<<NGATE+NSCOR, 256, GSC_SMEM>>>(question, response, maskp, emb_q, emb_r,
                                                  pAGG, Wih, lb, pG, topk);
    lstm_pw_k<<<(NN*DD + 255)/256, 256>>>(pG, pL, out);

    ktfinal_k<<<NN/4, 256, KTF_SMEM>>>(question, skidx, skmask, emb_q, emb_s,
                                       pL, topk, Wq, bq, w_att, out);
}